// round 12
// baseline (speedup 1.0000x reference)
#include <cuda_runtime.h>
#include <cuda_fp16.h>
#include <stdint.h>
#include <math.h>

#define NMAX 100000
#define EMAX 1600000
#define NBMAX 128   // max scan blocks (n <= 131072)

// ---------------- scratch (device globals; no allocation allowed) ----------------
// Zero-state invariants: g_deg/g_tdesc zeroed by k_fill of the PREVIOUS run
// (statically zero on first run); g_eq/g_er2 zeroed by k_fill of THIS run.
__device__ __half g_feat1h[NMAX * 128];  // x @ W1 (fp16 for cheap edge gathers)
__device__ __half g_h1h[NMAX * 128];     // layer-1 output (fp16; GEMM2 A is fp16 anyway)
__device__ float g_el1[NMAX * 4];
__device__ float g_er1[NMAX * 4];
__device__ float2 g_eq[NMAX];            // (el2, q = feat2 . fcW) per node
__device__ float g_er2[NMAX];
__device__ float g_cc;                   // b2.fcW + fcb - thres
__device__ int g_deg[NMAX];
__device__ int g_off[NMAX + 1];
__device__ int g_cur[NMAX];
__device__ volatile unsigned long long g_tdesc[NBMAX];  // scan lookback: status<<32 | value
__device__ int g_csr[EMAX];              // src node per dst-sorted slot
__device__ uint2 g_wf1[4096];            // W1 fp16 mma fragments (hi only)
__device__ uint2 g_wf2[4096];            // W2 fp16 mma fragments (hi only)

// ---------------- fp16 helpers ----------------
__device__ __forceinline__ uint32_t hfpack(float a, float b) {
    __half2 t = __floats2half2_rn(a, b);
    return *reinterpret_cast<uint32_t*>(&t);
}

// ---------------- W fragments + classifier constant (main stream) ----------
// uint2 = {b0_hi, b1_hi} for mma.m16n8k16 col-major B.
__global__ void k_wsetup(const float* __restrict__ W1, const float* __restrict__ W2,
                         const float* __restrict__ b2, const float* __restrict__ fcW,
                         const float* __restrict__ fcb, const float* __restrict__ thres) {
    int i = blockIdx.x * blockDim.x + threadIdx.x;
    if (i < 8192) {
        const float* W = (i < 4096) ? W1 : W2;
        uint2* out = (i < 4096) ? g_wf1 : g_wf2;
        int idx = i & 4095;
        int lane = idx & 31;
        int nt = (idx >> 5) & 7;
        int kt = (idx >> 8) & 7;
        int cb = idx >> 11;
        int col = cb * 64 + nt * 8 + (lane >> 2);
        int tig = lane & 3;
        int k0 = kt * 16 + 2 * tig;
        uint2 o;
        o.x = hfpack(W[k0 * 128 + col], W[(k0 + 1) * 128 + col]);
        o.y = hfpack(W[(k0 + 8) * 128 + col], W[(k0 + 9) * 128 + col]);
        out[idx] = o;
    }
    if (blockIdx.x == 0 && threadIdx.x < 32) {
        int lane = threadIdx.x;
        float4 b = ((const float4*)b2)[lane];
        float4 wv = ((const float4*)fcW)[lane];
        float p = b.x * wv.x + b.y * wv.y + b.z * wv.z + b.w * wv.w;
        for (int o = 16; o; o >>= 1) p += __shfl_xor_sync(0xffffffffu, p, o);
        if (lane == 0) g_cc = p + fcb[0] - thres[0];
    }
}

// ---------------- CSR build (side stream) ----------------
// 4 edges per thread (int4) for MLP.
__global__ void k_hist(const int* __restrict__ dst, int e) {
    int j = (blockIdx.x * blockDim.x + threadIdx.x) * 4;
    if (j + 3 < e) {
        int4 d4 = *(const int4*)(dst + j);
        atomicAdd(&g_deg[d4.x], 1);
        atomicAdd(&g_deg[d4.y], 1);
        atomicAdd(&g_deg[d4.z], 1);
        atomicAdd(&g_deg[d4.w], 1);
    } else {
        for (int k = j; k < e; k++) atomicAdd(&g_deg[dst[k]], 1);
    }
}

// single-pass exclusive scan with WARP-PARALLEL decoupled lookback.
__global__ void k_scan(int n) {
    __shared__ int s[1024];
    __shared__ int sexcl;
    int b = blockIdx.x, t = threadIdx.x;
    int g = b * 1024 + t;
    int v = (g < n) ? g_deg[g] : 0;
    s[t] = v;
    __syncthreads();
    for (int o = 1; o < 1024; o <<= 1) {
        int x = (t >= o) ? s[t - o] : 0;
        __syncthreads();
        s[t] += x;
        __syncthreads();
    }
    if (t < 32) {
        int total = s[1023];
        int excl = 0;
        if (b == 0) {
            if (t == 0) g_tdesc[0] = (2ull << 32) | (unsigned)total;
        } else {
            if (t == 0) g_tdesc[b] = (1ull << 32) | (unsigned)total;
            int p = b - 1;
            bool done = false;
            while (!done) {
                int idx = p - t;
                unsigned long long d = (idx >= 0) ? g_tdesc[idx] : (2ull << 32);
                unsigned st = (unsigned)(d >> 32);
                if (__all_sync(0xffffffffu, st != 0u)) {
                    unsigned m2 = __ballot_sync(0xffffffffu, st == 2u);
                    int f = (int)__ffs(m2) - 1;          // nearest inclusive-prefix lane
                    int lim = (f < 0) ? 31 : f;
                    int val = (t <= lim && idx >= 0) ? (int)(unsigned)d : 0;
#pragma unroll
                    for (int o = 16; o; o >>= 1) val += __shfl_xor_sync(0xffffffffu, val, o);
                    excl += val;
                    if (f >= 0) done = true; else p -= 32;
                }
            }
            if (t == 0) g_tdesc[b] = (2ull << 32) | (unsigned)(excl + total);
        }
        if (t == 0) sexcl = excl;
    }
    __syncthreads();
    int ex = sexcl + s[t] - v;
    if (g <= n) g_off[g] = ex;
    if (g < n) g_cur[g] = ex;
}

// fill CSR (4 edges/thread) + restore zero-state (g_deg/g_tdesc for next run;
// g_eq/g_er2 for this run's gemm2 atomics)
__global__ void k_fill(const int* __restrict__ src, const int* __restrict__ dst,
                       int e, int n) {
    int i = blockIdx.x * blockDim.x + threadIdx.x;
    int j = i * 4;
    if (j + 3 < e) {
        int4 d4 = *(const int4*)(dst + j);
        int4 s4 = *(const int4*)(src + j);
        g_csr[atomicAdd(&g_cur[d4.x], 1)] = s4.x;
        g_csr[atomicAdd(&g_cur[d4.y], 1)] = s4.y;
        g_csr[atomicAdd(&g_cur[d4.z], 1)] = s4.z;
        g_csr[atomicAdd(&g_cur[d4.w], 1)] = s4.w;
    } else {
        for (int k = j; k < e; k++) {
            g_csr[atomicAdd(&g_cur[dst[k]], 1)] = src[k];
        }
    }
    if (i < n) {
        g_deg[i] = 0;
        g_eq[i] = make_float2(0.f, 0.f);
        g_er2[i] = 0.f;
    }
    if (i < NBMAX) g_tdesc[i] = 0ull;
}

// ---------------- mma / ldmatrix primitives ----------------
__device__ __forceinline__ void mma16816(float* c, const uint32_t* a, uint32_t b0, uint32_t b1) {
    asm volatile(
        "mma.sync.aligned.m16n8k16.row.col.f32.f16.f16.f32 "
        "{%0,%1,%2,%3}, {%4,%5,%6,%7}, {%8,%9}, {%0,%1,%2,%3};"
        : "+f"(c[0]), "+f"(c[1]), "+f"(c[2]), "+f"(c[3])
        : "r"(a[0]), "r"(a[1]), "r"(a[2]), "r"(a[3]), "r"(b0), "r"(b1));
}

__device__ __forceinline__ void ldsm4(uint32_t* r, uint32_t saddr) {
    asm volatile("ldmatrix.sync.aligned.m8n8.x4.shared.b16 {%0,%1,%2,%3}, [%4];"
                 : "=r"(r[0]), "=r"(r[1]), "=r"(r[2]), "=r"(r[3]) : "r"(saddr));
}

__device__ __forceinline__ float lrelu(float x) { return x >= 0.f ? x : 0.2f * x; }

#define XW 68   // padded X-tile row stride in 32-bit words

// ---------------- tensor-core GEMM: Y[n,128] = X[n,128] @ W[128,128] ----------------
// 512 threads (16 warps); CTA = 128 rows x 128 cols. Warp = 32 rows x 32 cols.
// A fp16, W fp16, fp32 acc. A frags via ldmatrix.x4.
// MODE 1 (layer 1): X fp32; store Y fp16 + direct el1/er1 (head == col group).
// MODE 2 (layer 2): X fp16; NO Y store; atomicAdd partial el2/er2/q per row.
template <int MODE>
__global__ __launch_bounds__(512, 2) void k_gemm_h(
    const void* __restrict__ Xv, const uint2* __restrict__ wfg,
    __half2* __restrict__ Y, int n,
    const float* __restrict__ attl, const float* __restrict__ attr,
    const float* __restrict__ fcw,
    float* __restrict__ elOut, float* __restrict__ erOut,
    float2* __restrict__ eqOut)
{
    extern __shared__ uint32_t xhi[];         // 128*XW words (34.8 KB)
    int tid = threadIdx.x;
    int row0 = blockIdx.x << 7;

    int nrow = n - row0;
    if (nrow > 128) nrow = 128;
    if (MODE == 1) {
        const float4* X4 = (const float4*)Xv;
        for (int i = tid; i < 4096; i += 512) {   // 128 rows x 32 float4
            int r = i >> 5, c = i & 31;
            float4 v = make_float4(0.f, 0.f, 0.f, 0.f);
            if (r < nrow) v = X4[(size_t)(row0 + r) * 32 + c];
            uint2 hi;
            hi.x = hfpack(v.x, v.y);
            hi.y = hfpack(v.z, v.w);
            *(uint2*)&xhi[r * XW + 2 * c] = hi;
        }
    } else {
        const uint2* X2 = (const uint2*)Xv;       // fp16 rows: 32 uint2 per row
        for (int i = tid; i < 4096; i += 512) {
            int r = i >> 5, c = i & 31;
            uint2 v = make_uint2(0u, 0u);
            if (r < nrow) v = X2[(size_t)(row0 + r) * 32 + c];
            *(uint2*)&xhi[r * XW + 2 * c] = v;
        }
    }
    __syncthreads();

    int warp = tid >> 5, lane = tid & 31;
    int cg = warp & 3;          // col group: cols cg*32..cg*32+31 (head cg in layer 1)
    int rg = warp >> 2;         // row group: rows rg*32..rg*32+31
    int gID = lane >> 2, tig = lane & 3;

    uint32_t sbase;
    asm("{ .reg .u64 t; cvta.to.shared.u64 t, %1; cvt.u32.u64 %0, t; }"
        : "=r"(sbase) : "l"(xhi));
    int mr = (lane & 7) + ((lane >> 3) & 1) * 8;   // ldmatrix row within 16
    int kw = ((lane >> 4) & 1) * 4;                // +4 words for k8..15

    float acc[2][4][4];
#pragma unroll
    for (int t = 0; t < 2; t++)
#pragma unroll
        for (int nt = 0; nt < 4; nt++)
            acc[t][nt][0] = acc[t][nt][1] = acc[t][nt][2] = acc[t][nt][3] = 0.f;

    int cb = cg >> 1;
    const uint2* wbase = wfg + (cb << 11) + (((cg & 1) * 4) << 5) + lane;

#pragma unroll
    for (int kt = 0; kt < 8; kt++) {
        const uint2* wk = wbase + (kt << 8);
        uint2 bfr[4];
#pragma unroll
        for (int nt = 0; nt < 4; nt++) bfr[nt] = __ldg(wk + (nt << 5));
#pragma unroll
        for (int t = 0; t < 2; t++) {
            int row = rg * 32 + t * 16 + mr;
            uint32_t saddr = sbase + (uint32_t)(row * XW + kt * 8 + kw) * 4u;
            uint32_t ah[4];
            ldsm4(ah, saddr);
#pragma unroll
            for (int nt = 0; nt < 4; nt++)
                mma16816(acc[t][nt], ah, bfr[nt].x, bfr[nt].y);
        }
    }

    if (MODE == 1) {
#pragma unroll
        for (int t = 0; t < 2; t++) {
            int r0 = row0 + rg * 32 + t * 16 + gID;
            int r1 = r0 + 8;
#pragma unroll
            for (int nt = 0; nt < 4; nt++) {
                int c2 = cg * 16 + nt * 4 + tig;   // half2 column index
                if (r0 < n) Y[(size_t)r0 * 64 + c2] = __floats2half2_rn(acc[t][nt][0], acc[t][nt][1]);
                if (r1 < n) Y[(size_t)r1 * 64 + c2] = __floats2half2_rn(acc[t][nt][2], acc[t][nt][3]);
            }
        }
#pragma unroll
        for (int t = 0; t < 2; t++) {
            float el0 = 0.f, er0 = 0.f, el1v = 0.f, er1v = 0.f;
#pragma unroll
            for (int nt = 0; nt < 4; nt++) {
                int c2 = cg * 16 + nt * 4 + tig;
                float2 av = ((const float2*)attl)[c2];
                float2 rv = ((const float2*)attr)[c2];
                el0  += acc[t][nt][0] * av.x + acc[t][nt][1] * av.y;
                er0  += acc[t][nt][0] * rv.x + acc[t][nt][1] * rv.y;
                el1v += acc[t][nt][2] * av.x + acc[t][nt][3] * av.y;
                er1v += acc[t][nt][2] * rv.x + acc[t][nt][3] * rv.y;
            }
#pragma unroll
            for (int o = 1; o <= 2; o <<= 1) {
                el0  += __shfl_xor_sync(0xffffffffu, el0, o);
                er0  += __shfl_xor_sync(0xffffffffu, er0, o);
                el1v += __shfl_xor_sync(0xffffffffu, el1v, o);
                er1v += __shfl_xor_sync(0xffffffffu, er1v, o);
            }
            if (tig == 0) {
                int r0 = row0 + rg * 32 + t * 16 + gID;
                int r1 = r0 + 8;
                if (r0 < n) { elOut[r0 * 4 + cg] = el0;  erOut[r0 * 4 + cg] = er0; }
                if (r1 < n) { elOut[r1 * 4 + cg] = el1v; erOut[r1 * 4 + cg] = er1v; }
            }
        }
    } else {
#pragma unroll
        for (int t = 0; t < 2; t++) {
            float el0 = 0.f, er0 = 0.f, q0 = 0.f, el1v = 0.f, er1v = 0.f, q1v = 0.f;
#pragma unroll
            for (int nt = 0; nt < 4; nt++) {
                int c2 = cg * 16 + nt * 4 + tig;
                float2 av = ((const float2*)attl)[c2];
                float2 rv = ((const float2*)attr)[c2];
                float2 qv = ((const float2*)fcw)[c2];
                el0  += acc[t][nt][0] * av.x + acc[t][nt][1] * av.y;
                er0  += acc[t][nt][0] * rv.x + acc[t][nt][1] * rv.y;
                q0   += acc[t][nt][0] * qv.x + acc[t][nt][1] * qv.y;
                el1v += acc[t][nt][2] * av.x + acc[t][nt][3] * av.y;
                er1v += acc[t][nt][2] * rv.x + acc[t][nt][3] * rv.y;
                q1v  += acc[t][nt][2] * qv.x + acc[t][nt][3] * qv.y;
            }
#pragma unroll
            for (int o = 1; o <= 2; o <<= 1) {
                el0  += __shfl_xor_sync(0xffffffffu, el0, o);
                er0  += __shfl_xor_sync(0xffffffffu, er0, o);
                q0   += __shfl_xor_sync(0xffffffffu, q0, o);
                el1v += __shfl_xor_sync(0xffffffffu, el1v, o);
                er1v += __shfl_xor_sync(0xffffffffu, er1v, o);
                q1v  += __shfl_xor_sync(0xffffffffu, q1v, o);
            }
            if (tig == 0) {
                int r0 = row0 + rg * 32 + t * 16 + gID;
                int r1 = r0 + 8;
                if (r0 < n) {
                    atomicAdd(&eqOut[r0].x, el0);
                    atomicAdd(&eqOut[r0].y, q0);
                    atomicAdd(&erOut[r0], er0);
                }
                if (r1 < n) {
                    atomicAdd(&eqOut[r1].x, el1v);
                    atomicAdd(&eqOut[r1].y, q1v);
                    atomicAdd(&erOut[r1], er1v);
                }
            }
        }
    }
}

// ---------------- GAT aggregation, layer 1 (H=4), single pass, warp per node ------
// Feature-phase gathers are UNCONDITIONAL (8 per chunk, invalid lanes carry s=0,
// w=0) so the 8 loads batch back-to-back -> MLP 8.
__global__ void k_agg1(const __half* __restrict__ feat, const float* __restrict__ bias,
                       uint2* __restrict__ out, int n) {
    int w = (blockIdx.x * blockDim.x + threadIdx.x) >> 5;
    int lane = threadIdx.x & 31;
    if (w >= n) return;
    int s0 = g_off[w], s1 = g_off[w + 1];
    int hw = lane & 3;    // weight-phase head
    int hf = lane >> 3;   // feature-phase head
    int c = lane >> 2;    // edge-in-chunk for weight phase
    float er_w = g_er1[w * 4 + hw];

    float dacc = 0.f;
    float4 acc = make_float4(0.f, 0.f, 0.f, 0.f);
    for (int base = s0; base < s1; base += 8) {
        int cnt = s1 - base;
        int s_c = 0;
        float wv = 0.f;
        if (c < cnt) {
            s_c = g_csr[base + c];
            wv = __expf(lrelu(g_el1[s_c * 4 + hw] + er_w));
        }
        dacc += wv;
        int sArr[8];
        float whA[8];
#pragma unroll
        for (int c2 = 0; c2 < 8; c2++) {
            whA[c2] = __shfl_sync(0xffffffffu, wv, c2 * 4 + hf);
            sArr[c2] = __shfl_sync(0xffffffffu, s_c, c2 * 4);
        }
        uint2 uu[8];
#pragma unroll
        for (int c2 = 0; c2 < 8; c2++)
            uu[c2] = ((const uint2*)feat)[(size_t)sArr[c2] * 32 + lane];
#pragma unroll
        for (int c2 = 0; c2 < 8; c2++) {
            float2 f0 = __half22float2(*(__half2*)&uu[c2].x);
            float2 f1 = __half22float2(*(__half2*)&uu[c2].y);
            float wh = whA[c2];
            acc.x = fmaf(f0.x, wh, acc.x);
            acc.y = fmaf(f0.y, wh, acc.y);
            acc.z = fmaf(f1.x, wh, acc.z);
            acc.w = fmaf(f1.y, wh, acc.w);
        }
    }
    dacc += __shfl_xor_sync(0xffffffffu, dacc, 4);
    dacc += __shfl_xor_sync(0xffffffffu, dacc, 8);
    dacc += __shfl_xor_sync(0xffffffffu, dacc, 16);
    float dh = __shfl_sync(0xffffffffu, dacc, hf);
    float inv = (dh > 0.f) ? (1.f / dh) : 0.f;

    float4 b = ((const float4*)bias)[lane];
    acc.x = fmaxf(fmaf(acc.x, inv, b.x), 0.f);
    acc.y = fmaxf(fmaf(acc.y, inv, b.y), 0.f);
    acc.z = fmaxf(fmaf(acc.z, inv, b.z), 0.f);
    acc.w = fmaxf(fmaf(acc.w, inv, b.w), 0.f);
    uint2 st;
    st.x = hfpack(acc.x, acc.y);
    st.y = hfpack(acc.z, acc.w);
    out[(size_t)w * 32 + lane] = st;
}

// ---------------- layer 2 aggregation (scalar) + classifier, half-warp per node ----
__global__ void k_agg2(float* __restrict__ out, int n) {
    int w = (blockIdx.x * blockDim.x + threadIdx.x) >> 4;
    int sub = threadIdx.x & 15;
    if (w >= n) return;
    int s0 = g_off[w], s1 = g_off[w + 1];
    float er = g_er2[w];

    float wsum = 0.f, wq = 0.f;
    for (int j = s0 + sub; j < s1; j += 16) {
        int s = g_csr[j];
        float2 v = g_eq[s];                       // (el2[s], q[s]) one 8B load
        float wv = __expf(lrelu(v.x + er));
        wsum += wv;
        wq = fmaf(wv, v.y, wq);
    }
#pragma unroll
    for (int o = 8; o; o >>= 1) {
        wsum += __shfl_xor_sync(0xffffffffu, wsum, o);
        wq   += __shfl_xor_sync(0xffffffffu, wq, o);
    }
    if (sub == 0) out[w] = ((wsum > 0.f) ? (wq / wsum) : 0.f) + g_cc;
}

// ---------------- launch ----------------
extern "C" void kernel_launch(void* const* d_in, const int* in_sizes, int n_in,
                              void* d_out, int out_size) {
    const float* features = (const float*)d_in[0];
    const float* W1 = (const float*)d_in[1];
    const float* al1 = (const float*)d_in[2];
    const float* ar1 = (const float*)d_in[3];
    const float* b1 = (const float*)d_in[4];
    const float* W2 = (const float*)d_in[5];
    const float* al2 = (const float*)d_in[6];
    const float* ar2 = (const float*)d_in[7];
    const float* b2 = (const float*)d_in[8];
    const float* fcW = (const float*)d_in[9];
    const float* fcb = (const float*)d_in[10];
    const float* thres = (const float*)d_in[11];
    const int* src = (const int*)d_in[12];
    const int* dst = (const int*)d_in[13];
    float* out = (float*)d_out;

    int n = in_sizes[0] / 128;
    int e = in_sizes[12];
    int nb = (n + 1023) / 1024;

    __half *p_feat1h, *p_h1h;
    float *p_el1, *p_er1, *p_er2;
    float2* p_eq;
    cudaGetSymbolAddress((void**)&p_feat1h, g_feat1h);
    cudaGetSymbolAddress((void**)&p_h1h, g_h1h);
    cudaGetSymbolAddress((void**)&p_el1, g_el1);
    cudaGetSymbolAddress((void**)&p_er1, g_er1);
    cudaGetSymbolAddress((void**)&p_eq, g_eq);
    cudaGetSymbolAddress((void**)&p_er2, g_er2);
    uint2 *p_wf1, *p_wf2;
    cudaGetSymbolAddress((void**)&p_wf1, g_wf1);
    cudaGetSymbolAddress((void**)&p_wf2, g_wf2);

    const int GEMM_SMEM = 128 * XW * 4;  // 34816
    cudaFuncSetAttribute(k_gemm_h<1>, cudaFuncAttributeMaxDynamicSharedMemorySize, GEMM_SMEM);
    cudaFuncSetAttribute(k_gemm_h<2>, cudaFuncAttributeMaxDynamicSharedMemorySize, GEMM_SMEM);

    int e4 = (e + 3) / 4;
    int eb4 = (e4 + 255) / 256;         // 4 edges per thread
    int wblk = (n + 7) / 8;             // warp per node, 256-thread blocks
    int hblk = (n + 15) / 16;           // half-warp per node
    int gblk = (n + 127) / 128;         // gemm grid (512-thread CTAs)

    // fork-join resources (leaked intentionally: destroying during capture is illegal;
    // kernel_launch is called only a handful of times, never per-replay)
    cudaStream_t s2;
    cudaStreamCreateWithFlags(&s2, cudaStreamNonBlocking);
    cudaEvent_t e1, e2;
    cudaEventCreateWithFlags(&e1, cudaEventDisableTiming);
    cudaEventCreateWithFlags(&e2, cudaEventDisableTiming);

    // fork: CSR chain (hist -> scan -> fill) on s2 starts immediately;
    // main stream does wsetup -> GEMM1 concurrently.
    cudaEventRecord(e1, 0);
    cudaStreamWaitEvent(s2, e1, 0);
    k_hist<<<eb4, 256, 0, s2>>>(dst, e);
    k_scan<<<nb, 1024, 0, s2>>>(n);
    k_fill<<<eb4, 256, 0, s2>>>(src, dst, e, n);
    cudaEventRecord(e2, s2);             // CSR + zeroed eq/er2 ready

    k_wsetup<<<32, 256>>>(W1, W2, b2, fcW, fcb, thres);
    k_gemm_h<1><<<gblk, 512, GEMM_SMEM>>>(features, p_wf1, (__half2*)p_feat1h, n,
                                          al1, ar1, nullptr, p_el1, p_er1, nullptr);

    // join: agg1 needs GEMM1 outputs + CSR; gemm2's atomics need zeroed eq/er2
    cudaStreamWaitEvent(0, e2, 0);
    k_agg1<<<wblk, 256>>>(p_feat1h, b1, (uint2*)p_h1h, n);
    k_gemm_h<2><<<gblk, 512, GEMM_SMEM>>>(p_h1h, p_wf2, nullptr, n,
                                          al2, ar2, fcW, nullptr, p_er2, p_eq);
    k_agg2<<<hblk, 256>>>(out, n);
}

// round 13
// speedup vs baseline: 1.3164x; 1.3164x over previous
#include <cuda_runtime.h>
#include <cuda_fp16.h>
#include <stdint.h>
#include <math.h>

#define NMAX 100000
#define EMAX 1600000
#define NBMAX 128   // max scan blocks (n <= 131072)

// ---------------- scratch (device globals; no allocation allowed) ----------------
// Zero-state invariants: g_deg/g_tdesc zeroed by k_fill of the PREVIOUS run
// (statically zero on first run); g_eq/g_er2 zeroed by k_fill of THIS run.
__device__ __half g_feat1h[NMAX * 128];  // x @ W1 (fp16 for cheap edge gathers)
__device__ __half g_h1h[NMAX * 128];     // layer-1 output (fp16; GEMM2 A is fp16 anyway)
__device__ float g_el1[NMAX * 4];
__device__ float g_er1[NMAX * 4];
__device__ float2 g_eq[NMAX];            // (el2, q = feat2 . fcW) per node
__device__ float g_er2[NMAX];
__device__ float g_cc;                   // b2.fcW + fcb - thres
__device__ int g_deg[NMAX];
__device__ int g_off[NMAX + 1];
__device__ int g_ord[EMAX];              // per-edge ordinal within its dst (from hist)
__device__ volatile unsigned long long g_tdesc[NBMAX];  // scan lookback: status<<32 | value
__device__ int g_csr[EMAX];              // src node per dst-sorted slot
__device__ uint2 g_wf1[4096];            // W1 fp16 mma fragments (hi only)
__device__ uint2 g_wf2[4096];            // W2 fp16 mma fragments (hi only)

// ---------------- fp16 helpers ----------------
__device__ __forceinline__ uint32_t hfpack(float a, float b) {
    __half2 t = __floats2half2_rn(a, b);
    return *reinterpret_cast<uint32_t*>(&t);
}

// ---------------- W fragments + classifier constant (main stream) ----------
// uint2 = {b0_hi, b1_hi} for mma.m16n8k16 col-major B.
__global__ void k_wsetup(const float* __restrict__ W1, const float* __restrict__ W2,
                         const float* __restrict__ b2, const float* __restrict__ fcW,
                         const float* __restrict__ fcb, const float* __restrict__ thres) {
    int i = blockIdx.x * blockDim.x + threadIdx.x;
    if (i < 8192) {
        const float* W = (i < 4096) ? W1 : W2;
        uint2* out = (i < 4096) ? g_wf1 : g_wf2;
        int idx = i & 4095;
        int lane = idx & 31;
        int nt = (idx >> 5) & 7;
        int kt = (idx >> 8) & 7;
        int cb = idx >> 11;
        int col = cb * 64 + nt * 8 + (lane >> 2);
        int tig = lane & 3;
        int k0 = kt * 16 + 2 * tig;
        uint2 o;
        o.x = hfpack(W[k0 * 128 + col], W[(k0 + 1) * 128 + col]);
        o.y = hfpack(W[(k0 + 8) * 128 + col], W[(k0 + 9) * 128 + col]);
        out[idx] = o;
    }
    if (blockIdx.x == 0 && threadIdx.x < 32) {
        int lane = threadIdx.x;
        float4 b = ((const float4*)b2)[lane];
        float4 wv = ((const float4*)fcW)[lane];
        float p = b.x * wv.x + b.y * wv.y + b.z * wv.z + b.w * wv.w;
        for (int o = 16; o; o >>= 1) p += __shfl_xor_sync(0xffffffffu, p, o);
        if (lane == 0) g_cc = p + fcb[0] - thres[0];
    }
}

// ---------------- CSR build (side stream) ----------------
// hist: count degrees AND record each edge's ordinal within its destination.
__global__ void k_hist(const int* __restrict__ dst, int e) {
    int i = blockIdx.x * blockDim.x + threadIdx.x;
    if (i < e) g_ord[i] = atomicAdd(&g_deg[dst[i]], 1);
}

// single-pass exclusive scan with WARP-PARALLEL decoupled lookback.
__global__ void k_scan(int n) {
    __shared__ int s[1024];
    __shared__ int sexcl;
    int b = blockIdx.x, t = threadIdx.x;
    int g = b * 1024 + t;
    int v = (g < n) ? g_deg[g] : 0;
    s[t] = v;
    __syncthreads();
    for (int o = 1; o < 1024; o <<= 1) {
        int x = (t >= o) ? s[t - o] : 0;
        __syncthreads();
        s[t] += x;
        __syncthreads();
    }
    if (t < 32) {
        int total = s[1023];
        int excl = 0;
        if (b == 0) {
            if (t == 0) g_tdesc[0] = (2ull << 32) | (unsigned)total;
        } else {
            if (t == 0) g_tdesc[b] = (1ull << 32) | (unsigned)total;
            int p = b - 1;
            bool done = false;
            while (!done) {
                int idx = p - t;
                unsigned long long d = (idx >= 0) ? g_tdesc[idx] : (2ull << 32);
                unsigned st = (unsigned)(d >> 32);
                if (__all_sync(0xffffffffu, st != 0u)) {
                    unsigned m2 = __ballot_sync(0xffffffffu, st == 2u);
                    int f = (int)__ffs(m2) - 1;          // nearest inclusive-prefix lane
                    int lim = (f < 0) ? 31 : f;
                    int val = (t <= lim && idx >= 0) ? (int)(unsigned)d : 0;
#pragma unroll
                    for (int o = 16; o; o >>= 1) val += __shfl_xor_sync(0xffffffffu, val, o);
                    excl += val;
                    if (f >= 0) done = true; else p -= 32;
                }
            }
            if (t == 0) g_tdesc[b] = (2ull << 32) | (unsigned)(excl + total);
        }
        if (t == 0) sexcl = excl;
    }
    __syncthreads();
    int ex = sexcl + s[t] - v;
    if (g <= n) g_off[g] = ex;
}

// fill CSR: NO atomics (slot = off[dst] + ord), + restore zero-state
// (g_deg/g_tdesc for next run; g_eq/g_er2 for this run's gemm2 atomics)
__global__ void k_fill(const int* __restrict__ src, const int* __restrict__ dst,
                       int e, int n) {
    int i = blockIdx.x * blockDim.x + threadIdx.x;
    if (i < e) {
        int d = dst[i];
        g_csr[g_off[d] + g_ord[i]] = src[i];
    }
    if (i < n) {
        g_deg[i] = 0;
        g_eq[i] = make_float2(0.f, 0.f);
        g_er2[i] = 0.f;
    }
    if (i < NBMAX) g_tdesc[i] = 0ull;
}

// ---------------- mma / ldmatrix primitives ----------------
__device__ __forceinline__ void mma16816(float* c, const uint32_t* a, uint32_t b0, uint32_t b1) {
    asm volatile(
        "mma.sync.aligned.m16n8k16.row.col.f32.f16.f16.f32 "
        "{%0,%1,%2,%3}, {%4,%5,%6,%7}, {%8,%9}, {%0,%1,%2,%3};"
        : "+f"(c[0]), "+f"(c[1]), "+f"(c[2]), "+f"(c[3])
        : "r"(a[0]), "r"(a[1]), "r"(a[2]), "r"(a[3]), "r"(b0), "r"(b1));
}

__device__ __forceinline__ void ldsm4(uint32_t* r, uint32_t saddr) {
    asm volatile("ldmatrix.sync.aligned.m8n8.x4.shared.b16 {%0,%1,%2,%3}, [%4];"
                 : "=r"(r[0]), "=r"(r[1]), "=r"(r[2]), "=r"(r[3]) : "r"(saddr));
}

__device__ __forceinline__ float lrelu(float x) { return x >= 0.f ? x : 0.2f * x; }

#define XW 68   // padded X-tile row stride in 32-bit words

// ---------------- tensor-core GEMM: Y[n,128] = X[n,128] @ W[128,128] ----------------
// 512 threads (16 warps); CTA = 128 rows x 128 cols. Warp = 32 rows x 32 cols.
// A fp16, W fp16, fp32 acc. A frags via ldmatrix.x4.
// MODE 1 (layer 1): X fp32; store Y fp16 + direct el1/er1 (head == col group).
// MODE 2 (layer 2): X fp16; NO Y store; atomicAdd partial el2/er2/q per row.
template <int MODE>
__global__ __launch_bounds__(512, 2) void k_gemm_h(
    const void* __restrict__ Xv, const uint2* __restrict__ wfg,
    __half2* __restrict__ Y, int n,
    const float* __restrict__ attl, const float* __restrict__ attr,
    const float* __restrict__ fcw,
    float* __restrict__ elOut, float* __restrict__ erOut,
    float2* __restrict__ eqOut)
{
    extern __shared__ uint32_t xhi[];         // 128*XW words (34.8 KB)
    int tid = threadIdx.x;
    int row0 = blockIdx.x << 7;

    int nrow = n - row0;
    if (nrow > 128) nrow = 128;
    if (MODE == 1) {
        const float4* X4 = (const float4*)Xv;
        for (int i = tid; i < 4096; i += 512) {   // 128 rows x 32 float4
            int r = i >> 5, c = i & 31;
            float4 v = make_float4(0.f, 0.f, 0.f, 0.f);
            if (r < nrow) v = X4[(size_t)(row0 + r) * 32 + c];
            uint2 hi;
            hi.x = hfpack(v.x, v.y);
            hi.y = hfpack(v.z, v.w);
            *(uint2*)&xhi[r * XW + 2 * c] = hi;
        }
    } else {
        const uint2* X2 = (const uint2*)Xv;       // fp16 rows: 32 uint2 per row
        for (int i = tid; i < 4096; i += 512) {
            int r = i >> 5, c = i & 31;
            uint2 v = make_uint2(0u, 0u);
            if (r < nrow) v = X2[(size_t)(row0 + r) * 32 + c];
            *(uint2*)&xhi[r * XW + 2 * c] = v;
        }
    }
    __syncthreads();

    int warp = tid >> 5, lane = tid & 31;
    int cg = warp & 3;          // col group: cols cg*32..cg*32+31 (head cg in layer 1)
    int rg = warp >> 2;         // row group: rows rg*32..rg*32+31
    int gID = lane >> 2, tig = lane & 3;

    uint32_t sbase;
    asm("{ .reg .u64 t; cvta.to.shared.u64 t, %1; cvt.u32.u64 %0, t; }"
        : "=r"(sbase) : "l"(xhi));
    int mr = (lane & 7) + ((lane >> 3) & 1) * 8;   // ldmatrix row within 16
    int kw = ((lane >> 4) & 1) * 4;                // +4 words for k8..15

    float acc[2][4][4];
#pragma unroll
    for (int t = 0; t < 2; t++)
#pragma unroll
        for (int nt = 0; nt < 4; nt++)
            acc[t][nt][0] = acc[t][nt][1] = acc[t][nt][2] = acc[t][nt][3] = 0.f;

    int cb = cg >> 1;
    const uint2* wbase = wfg + (cb << 11) + (((cg & 1) * 4) << 5) + lane;

#pragma unroll
    for (int kt = 0; kt < 8; kt++) {
        const uint2* wk = wbase + (kt << 8);
        uint2 bfr[4];
#pragma unroll
        for (int nt = 0; nt < 4; nt++) bfr[nt] = __ldg(wk + (nt << 5));
#pragma unroll
        for (int t = 0; t < 2; t++) {
            int row = rg * 32 + t * 16 + mr;
            uint32_t saddr = sbase + (uint32_t)(row * XW + kt * 8 + kw) * 4u;
            uint32_t ah[4];
            ldsm4(ah, saddr);
#pragma unroll
            for (int nt = 0; nt < 4; nt++)
                mma16816(acc[t][nt], ah, bfr[nt].x, bfr[nt].y);
        }
    }

    if (MODE == 1) {
#pragma unroll
        for (int t = 0; t < 2; t++) {
            int r0 = row0 + rg * 32 + t * 16 + gID;
            int r1 = r0 + 8;
#pragma unroll
            for (int nt = 0; nt < 4; nt++) {
                int c2 = cg * 16 + nt * 4 + tig;   // half2 column index
                if (r0 < n) Y[(size_t)r0 * 64 + c2] = __floats2half2_rn(acc[t][nt][0], acc[t][nt][1]);
                if (r1 < n) Y[(size_t)r1 * 64 + c2] = __floats2half2_rn(acc[t][nt][2], acc[t][nt][3]);
            }
        }
#pragma unroll
        for (int t = 0; t < 2; t++) {
            float el0 = 0.f, er0 = 0.f, el1v = 0.f, er1v = 0.f;
#pragma unroll
            for (int nt = 0; nt < 4; nt++) {
                int c2 = cg * 16 + nt * 4 + tig;
                float2 av = ((const float2*)attl)[c2];
                float2 rv = ((const float2*)attr)[c2];
                el0  += acc[t][nt][0] * av.x + acc[t][nt][1] * av.y;
                er0  += acc[t][nt][0] * rv.x + acc[t][nt][1] * rv.y;
                el1v += acc[t][nt][2] * av.x + acc[t][nt][3] * av.y;
                er1v += acc[t][nt][2] * rv.x + acc[t][nt][3] * rv.y;
            }
#pragma unroll
            for (int o = 1; o <= 2; o <<= 1) {
                el0  += __shfl_xor_sync(0xffffffffu, el0, o);
                er0  += __shfl_xor_sync(0xffffffffu, er0, o);
                el1v += __shfl_xor_sync(0xffffffffu, el1v, o);
                er1v += __shfl_xor_sync(0xffffffffu, er1v, o);
            }
            if (tig == 0) {
                int r0 = row0 + rg * 32 + t * 16 + gID;
                int r1 = r0 + 8;
                if (r0 < n) { elOut[r0 * 4 + cg] = el0;  erOut[r0 * 4 + cg] = er0; }
                if (r1 < n) { elOut[r1 * 4 + cg] = el1v; erOut[r1 * 4 + cg] = er1v; }
            }
        }
    } else {
#pragma unroll
        for (int t = 0; t < 2; t++) {
            float el0 = 0.f, er0 = 0.f, q0 = 0.f, el1v = 0.f, er1v = 0.f, q1v = 0.f;
#pragma unroll
            for (int nt = 0; nt < 4; nt++) {
                int c2 = cg * 16 + nt * 4 + tig;
                float2 av = ((const float2*)attl)[c2];
                float2 rv = ((const float2*)attr)[c2];
                float2 qv = ((const float2*)fcw)[c2];
                el0  += acc[t][nt][0] * av.x + acc[t][nt][1] * av.y;
                er0  += acc[t][nt][0] * rv.x + acc[t][nt][1] * rv.y;
                q0   += acc[t][nt][0] * qv.x + acc[t][nt][1] * qv.y;
                el1v += acc[t][nt][2] * av.x + acc[t][nt][3] * av.y;
                er1v += acc[t][nt][2] * rv.x + acc[t][nt][3] * rv.y;
                q1v  += acc[t][nt][2] * qv.x + acc[t][nt][3] * qv.y;
            }
#pragma unroll
            for (int o = 1; o <= 2; o <<= 1) {
                el0  += __shfl_xor_sync(0xffffffffu, el0, o);
                er0  += __shfl_xor_sync(0xffffffffu, er0, o);
                q0   += __shfl_xor_sync(0xffffffffu, q0, o);
                el1v += __shfl_xor_sync(0xffffffffu, el1v, o);
                er1v += __shfl_xor_sync(0xffffffffu, er1v, o);
                q1v  += __shfl_xor_sync(0xffffffffu, q1v, o);
            }
            if (tig == 0) {
                int r0 = row0 + rg * 32 + t * 16 + gID;
                int r1 = r0 + 8;
                if (r0 < n) {
                    atomicAdd(&eqOut[r0].x, el0);
                    atomicAdd(&eqOut[r0].y, q0);
                    atomicAdd(&erOut[r0], er0);
                }
                if (r1 < n) {
                    atomicAdd(&eqOut[r1].x, el1v);
                    atomicAdd(&eqOut[r1].y, q1v);
                    atomicAdd(&erOut[r1], er1v);
                }
            }
        }
    }
}

// ---------------- GAT aggregation, layer 1 (H=4), single pass, warp per node ------
__global__ void k_agg1(const __half* __restrict__ feat, const float* __restrict__ bias,
                       uint2* __restrict__ out, int n) {
    int w = (blockIdx.x * blockDim.x + threadIdx.x) >> 5;
    int lane = threadIdx.x & 31;
    if (w >= n) return;
    int s0 = g_off[w], s1 = g_off[w + 1];
    int hw = lane & 3;    // weight-phase head
    int hf = lane >> 3;   // feature-phase head
    int c = lane >> 2;    // edge-in-chunk for weight phase
    float er_w = g_er1[w * 4 + hw];

    float dacc = 0.f;
    float4 acc = make_float4(0.f, 0.f, 0.f, 0.f);
    for (int base = s0; base < s1; base += 8) {
        int cnt = s1 - base;
        if (cnt > 8) cnt = 8;
        int s_c = 0;
        float wv = 0.f;
        if (c < cnt) {
            s_c = g_csr[base + c];
            wv = __expf(lrelu(g_el1[s_c * 4 + hw] + er_w));
        }
        dacc += wv;
#pragma unroll
        for (int c2 = 0; c2 < 8; c2++) {
            if (c2 >= cnt) break;
            float wh = __shfl_sync(0xffffffffu, wv, c2 * 4 + hf);
            int s = __shfl_sync(0xffffffffu, s_c, c2 * 4);
            uint2 u = ((const uint2*)feat)[(size_t)s * 32 + lane];
            float2 f0 = __half22float2(*(__half2*)&u.x);
            float2 f1 = __half22float2(*(__half2*)&u.y);
            acc.x = fmaf(f0.x, wh, acc.x);
            acc.y = fmaf(f0.y, wh, acc.y);
            acc.z = fmaf(f1.x, wh, acc.z);
            acc.w = fmaf(f1.y, wh, acc.w);
        }
    }
    dacc += __shfl_xor_sync(0xffffffffu, dacc, 4);
    dacc += __shfl_xor_sync(0xffffffffu, dacc, 8);
    dacc += __shfl_xor_sync(0xffffffffu, dacc, 16);
    float dh = __shfl_sync(0xffffffffu, dacc, hf);
    float inv = (dh > 0.f) ? (1.f / dh) : 0.f;

    float4 b = ((const float4*)bias)[lane];
    acc.x = fmaxf(fmaf(acc.x, inv, b.x), 0.f);
    acc.y = fmaxf(fmaf(acc.y, inv, b.y), 0.f);
    acc.z = fmaxf(fmaf(acc.z, inv, b.z), 0.f);
    acc.w = fmaxf(fmaf(acc.w, inv, b.w), 0.f);
    uint2 st;
    st.x = hfpack(acc.x, acc.y);
    st.y = hfpack(acc.z, acc.w);
    out[(size_t)w * 32 + lane] = st;
}

// ---------------- layer 2 aggregation (scalar) + classifier, half-warp per node ----
__global__ void k_agg2(float* __restrict__ out, int n) {
    int w = (blockIdx.x * blockDim.x + threadIdx.x) >> 4;
    int sub = threadIdx.x & 15;
    if (w >= n) return;
    int s0 = g_off[w], s1 = g_off[w + 1];
    float er = g_er2[w];

    float wsum = 0.f, wq = 0.f;
    for (int j = s0 + sub; j < s1; j += 16) {
        int s = g_csr[j];
        float2 v = g_eq[s];                       // (el2[s], q[s]) one 8B load
        float wv = __expf(lrelu(v.x + er));
        wsum += wv;
        wq = fmaf(wv, v.y, wq);
    }
#pragma unroll
    for (int o = 8; o; o >>= 1) {
        wsum += __shfl_xor_sync(0xffffffffu, wsum, o);
        wq   += __shfl_xor_sync(0xffffffffu, wq, o);
    }
    if (sub == 0) out[w] = ((wsum > 0.f) ? (wq / wsum) : 0.f) + g_cc;
}

// ---------------- launch ----------------
extern "C" void kernel_launch(void* const* d_in, const int* in_sizes, int n_in,
                              void* d_out, int out_size) {
    const float* features = (const float*)d_in[0];
    const float* W1 = (const float*)d_in[1];
    const float* al1 = (const float*)d_in[2];
    const float* ar1 = (const float*)d_in[3];
    const float* b1 = (const float*)d_in[4];
    const float* W2 = (const float*)d_in[5];
    const float* al2 = (const float*)d_in[6];
    const float* ar2 = (const float*)d_in[7];
    const float* b2 = (const float*)d_in[8];
    const float* fcW = (const float*)d_in[9];
    const float* fcb = (const float*)d_in[10];
    const float* thres = (const float*)d_in[11];
    const int* src = (const int*)d_in[12];
    const int* dst = (const int*)d_in[13];
    float* out = (float*)d_out;

    int n = in_sizes[0] / 128;
    int e = in_sizes[12];
    int nb = (n + 1023) / 1024;

    __half *p_feat1h, *p_h1h;
    float *p_el1, *p_er1, *p_er2;
    float2* p_eq;
    cudaGetSymbolAddress((void**)&p_feat1h, g_feat1h);
    cudaGetSymbolAddress((void**)&p_h1h, g_h1h);
    cudaGetSymbolAddress((void**)&p_el1, g_el1);
    cudaGetSymbolAddress((void**)&p_er1, g_er1);
    cudaGetSymbolAddress((void**)&p_eq, g_eq);
    cudaGetSymbolAddress((void**)&p_er2, g_er2);
    uint2 *p_wf1, *p_wf2;
    cudaGetSymbolAddress((void**)&p_wf1, g_wf1);
    cudaGetSymbolAddress((void**)&p_wf2, g_wf2);

    const int GEMM_SMEM = 128 * XW * 4;  // 34816
    cudaFuncSetAttribute(k_gemm_h<1>, cudaFuncAttributeMaxDynamicSharedMemorySize, GEMM_SMEM);
    cudaFuncSetAttribute(k_gemm_h<2>, cudaFuncAttributeMaxDynamicSharedMemorySize, GEMM_SMEM);

    int eb = (e + 255) / 256;
    int wblk = (n + 7) / 8;             // warp per node, 256-thread blocks
    int hblk = (n + 15) / 16;           // half-warp per node
    int gblk = (n + 127) / 128;         // gemm grid (512-thread CTAs)

    // fork-join resources (leaked intentionally: destroying during capture is illegal;
    // kernel_launch is called only a handful of times, never per-replay)
    cudaStream_t s2;
    cudaStreamCreateWithFlags(&s2, cudaStreamNonBlocking);
    cudaEvent_t e1, e2;
    cudaEventCreateWithFlags(&e1, cudaEventDisableTiming);
    cudaEventCreateWithFlags(&e2, cudaEventDisableTiming);

    // fork: CSR chain (hist -> scan -> fill) on s2 starts immediately;
    // main stream does wsetup -> GEMM1 concurrently.
    cudaEventRecord(e1, 0);
    cudaStreamWaitEvent(s2, e1, 0);
    k_hist<<<eb, 256, 0, s2>>>(dst, e);
    k_scan<<<nb, 1024, 0, s2>>>(n);
    k_fill<<<eb, 256, 0, s2>>>(src, dst, e, n);
    cudaEventRecord(e2, s2);             // CSR + zeroed eq/er2 ready

    k_wsetup<<<32, 256>>>(W1, W2, b2, fcW, fcb, thres);
    k_gemm_h<1><<<gblk, 512, GEMM_SMEM>>>(features, p_wf1, (__half2*)p_feat1h, n,
                                          al1, ar1, nullptr, p_el1, p_er1, nullptr);

    // join: agg1 needs GEMM1 outputs + CSR; gemm2's atomics need zeroed eq/er2
    cudaStreamWaitEvent(0, e2, 0);
    k_agg1<<<wblk, 256>>>(p_feat1h, b1, (uint2*)p_h1h, n);
    k_gemm_h<2><<<gblk, 512, GEMM_SMEM>>>(p_h1h, p_wf2, nullptr, n,
                                          al2, ar2, fcW, nullptr, p_er2, p_eq);
    k_agg2<<<hblk, 256>>>(out, n);
}

// round 14
// speedup vs baseline: 1.3906x; 1.0563x over previous
#include <cuda_runtime.h>
#include <cuda_fp16.h>
#include <stdint.h>
#include <math.h>

#define NMAX 100000
#define EMAX 1600000
#define NBMAX 128   // max scan blocks (n <= 131072)

// ---------------- scratch (device globals; no allocation allowed) ----------------
// Zero-state invariants: g_deg/g_tdesc zeroed by k_fill of the PREVIOUS run
// (statically zero on first run); g_eq/g_er2 zeroed by k_fill of THIS run.
__device__ __half g_feat1h[NMAX * 128];  // x @ W1 (fp16 for cheap edge gathers)
__device__ __half g_h1h[NMAX * 128];     // layer-1 output (fp16; GEMM2 A is fp16 anyway)
__device__ float g_el1[NMAX * 4];
__device__ float g_er1[NMAX * 4];
__device__ float2 g_eq[NMAX];            // (el2, q = feat2 . fcW) per node
__device__ float g_er2[NMAX];
__device__ float g_cc;                   // b2.fcW + fcb - thres
__device__ int g_deg[NMAX];
__device__ int g_off[NMAX + 1];
__device__ int g_ord[EMAX];              // per-edge ordinal within its dst (from hist)
__device__ volatile unsigned long long g_tdesc[NBMAX];  // scan lookback: status<<32 | value
__device__ int g_csr[EMAX];              // src node per dst-sorted slot
__device__ uint2 g_wf1[4096];            // W1 fp16 mma fragments (hi only)
__device__ uint2 g_wf2[4096];            // W2 fp16 mma fragments (hi only)

// ---------------- fp16 helpers ----------------
__device__ __forceinline__ uint32_t hfpack(float a, float b) {
    __half2 t = __floats2half2_rn(a, b);
    return *reinterpret_cast<uint32_t*>(&t);
}

// ---------------- W fragments + classifier constant (main stream) ----------
// uint2 = {b0_hi, b1_hi} for mma.m16n8k16 col-major B.
__global__ void k_wsetup(const float* __restrict__ W1, const float* __restrict__ W2,
                         const float* __restrict__ b2, const float* __restrict__ fcW,
                         const float* __restrict__ fcb, const float* __restrict__ thres) {
    int i = blockIdx.x * blockDim.x + threadIdx.x;
    if (i < 8192) {
        const float* W = (i < 4096) ? W1 : W2;
        uint2* out = (i < 4096) ? g_wf1 : g_wf2;
        int idx = i & 4095;
        int lane = idx & 31;
        int nt = (idx >> 5) & 7;
        int kt = (idx >> 8) & 7;
        int cb = idx >> 11;
        int col = cb * 64 + nt * 8 + (lane >> 2);
        int tig = lane & 3;
        int k0 = kt * 16 + 2 * tig;
        uint2 o;
        o.x = hfpack(W[k0 * 128 + col], W[(k0 + 1) * 128 + col]);
        o.y = hfpack(W[(k0 + 8) * 128 + col], W[(k0 + 9) * 128 + col]);
        out[idx] = o;
    }
    if (blockIdx.x == 0 && threadIdx.x < 32) {
        int lane = threadIdx.x;
        float4 b = ((const float4*)b2)[lane];
        float4 wv = ((const float4*)fcW)[lane];
        float p = b.x * wv.x + b.y * wv.y + b.z * wv.z + b.w * wv.w;
        for (int o = 16; o; o >>= 1) p += __shfl_xor_sync(0xffffffffu, p, o);
        if (lane == 0) g_cc = p + fcb[0] - thres[0];
    }
}

// ---------------- CSR build (side stream) ----------------
// hist: count degrees AND record each edge's ordinal within its destination.
__global__ void k_hist(const int* __restrict__ dst, int e) {
    int i = blockIdx.x * blockDim.x + threadIdx.x;
    if (i < e) g_ord[i] = atomicAdd(&g_deg[dst[i]], 1);
}

// single-pass exclusive scan with WARP-PARALLEL decoupled lookback.
__global__ void k_scan(int n) {
    __shared__ int s[1024];
    __shared__ int sexcl;
    int b = blockIdx.x, t = threadIdx.x;
    int g = b * 1024 + t;
    int v = (g < n) ? g_deg[g] : 0;
    s[t] = v;
    __syncthreads();
    for (int o = 1; o < 1024; o <<= 1) {
        int x = (t >= o) ? s[t - o] : 0;
        __syncthreads();
        s[t] += x;
        __syncthreads();
    }
    if (t < 32) {
        int total = s[1023];
        int excl = 0;
        if (b == 0) {
            if (t == 0) g_tdesc[0] = (2ull << 32) | (unsigned)total;
        } else {
            if (t == 0) g_tdesc[b] = (1ull << 32) | (unsigned)total;
            int p = b - 1;
            bool done = false;
            while (!done) {
                int idx = p - t;
                unsigned long long d = (idx >= 0) ? g_tdesc[idx] : (2ull << 32);
                unsigned st = (unsigned)(d >> 32);
                if (__all_sync(0xffffffffu, st != 0u)) {
                    unsigned m2 = __ballot_sync(0xffffffffu, st == 2u);
                    int f = (int)__ffs(m2) - 1;          // nearest inclusive-prefix lane
                    int lim = (f < 0) ? 31 : f;
                    int val = (t <= lim && idx >= 0) ? (int)(unsigned)d : 0;
#pragma unroll
                    for (int o = 16; o; o >>= 1) val += __shfl_xor_sync(0xffffffffu, val, o);
                    excl += val;
                    if (f >= 0) done = true; else p -= 32;
                }
            }
            if (t == 0) g_tdesc[b] = (2ull << 32) | (unsigned)(excl + total);
        }
        if (t == 0) sexcl = excl;
    }
    __syncthreads();
    int ex = sexcl + s[t] - v;
    if (g <= n) g_off[g] = ex;
}

// fill CSR: NO atomics (slot = off[dst] + ord), + restore zero-state
// (g_deg/g_tdesc for next run; g_eq/g_er2 for this run's gemm2 atomics)
__global__ void k_fill(const int* __restrict__ src, const int* __restrict__ dst,
                       int e, int n) {
    int i = blockIdx.x * blockDim.x + threadIdx.x;
    if (i < e) {
        int d = dst[i];
        g_csr[g_off[d] + g_ord[i]] = src[i];
    }
    if (i < n) {
        g_deg[i] = 0;
        g_eq[i] = make_float2(0.f, 0.f);
        g_er2[i] = 0.f;
    }
    if (i < NBMAX) g_tdesc[i] = 0ull;
}

// ---------------- mma / ldmatrix primitives ----------------
__device__ __forceinline__ void mma16816(float* c, const uint32_t* a, uint32_t b0, uint32_t b1) {
    asm volatile(
        "mma.sync.aligned.m16n8k16.row.col.f32.f16.f16.f32 "
        "{%0,%1,%2,%3}, {%4,%5,%6,%7}, {%8,%9}, {%0,%1,%2,%3};"
        : "+f"(c[0]), "+f"(c[1]), "+f"(c[2]), "+f"(c[3])
        : "r"(a[0]), "r"(a[1]), "r"(a[2]), "r"(a[3]), "r"(b0), "r"(b1));
}

__device__ __forceinline__ void ldsm4(uint32_t* r, uint32_t saddr) {
    asm volatile("ldmatrix.sync.aligned.m8n8.x4.shared.b16 {%0,%1,%2,%3}, [%4];"
                 : "=r"(r[0]), "=r"(r[1]), "=r"(r[2]), "=r"(r[3]) : "r"(saddr));
}

__device__ __forceinline__ float lrelu(float x) { return x >= 0.f ? x : 0.2f * x; }

#define XW 68   // padded X-tile row stride in 32-bit words

// ---------------- tensor-core GEMM: Y[n,128] = X[n,128] @ W[128,128] ----------------
// 512 threads (16 warps); CTA = 128 rows x 128 cols. Warp = 32 rows x 32 cols.
// A fp16, W fp16, fp32 acc. A frags via ldmatrix.x4.
// MODE 1 (layer 1): X fp32; store Y fp16 + direct el1/er1 (head == col group).
// MODE 2 (layer 2): X fp16; NO Y store; atomicAdd partial el2/er2/q per row.
template <int MODE>
__global__ __launch_bounds__(512, 2) void k_gemm_h(
    const void* __restrict__ Xv, const uint2* __restrict__ wfg,
    __half2* __restrict__ Y, int n,
    const float* __restrict__ attl, const float* __restrict__ attr,
    const float* __restrict__ fcw,
    float* __restrict__ elOut, float* __restrict__ erOut,
    float2* __restrict__ eqOut)
{
    extern __shared__ uint32_t xhi[];         // 128*XW words (34.8 KB)
    int tid = threadIdx.x;
    int row0 = blockIdx.x << 7;

    int nrow = n - row0;
    if (nrow > 128) nrow = 128;
    if (MODE == 1) {
        const float4* X4 = (const float4*)Xv;
        for (int i = tid; i < 4096; i += 512) {   // 128 rows x 32 float4
            int r = i >> 5, c = i & 31;
            float4 v = make_float4(0.f, 0.f, 0.f, 0.f);
            if (r < nrow) v = X4[(size_t)(row0 + r) * 32 + c];
            uint2 hi;
            hi.x = hfpack(v.x, v.y);
            hi.y = hfpack(v.z, v.w);
            *(uint2*)&xhi[r * XW + 2 * c] = hi;
        }
    } else {
        const uint2* X2 = (const uint2*)Xv;       // fp16 rows: 32 uint2 per row
        for (int i = tid; i < 4096; i += 512) {
            int r = i >> 5, c = i & 31;
            uint2 v = make_uint2(0u, 0u);
            if (r < nrow) v = X2[(size_t)(row0 + r) * 32 + c];
            *(uint2*)&xhi[r * XW + 2 * c] = v;
        }
    }
    __syncthreads();

    int warp = tid >> 5, lane = tid & 31;
    int cg = warp & 3;          // col group: cols cg*32..cg*32+31 (head cg in layer 1)
    int rg = warp >> 2;         // row group: rows rg*32..rg*32+31
    int gID = lane >> 2, tig = lane & 3;

    uint32_t sbase;
    asm("{ .reg .u64 t; cvta.to.shared.u64 t, %1; cvt.u32.u64 %0, t; }"
        : "=r"(sbase) : "l"(xhi));
    int mr = (lane & 7) + ((lane >> 3) & 1) * 8;   // ldmatrix row within 16
    int kw = ((lane >> 4) & 1) * 4;                // +4 words for k8..15

    float acc[2][4][4];
#pragma unroll
    for (int t = 0; t < 2; t++)
#pragma unroll
        for (int nt = 0; nt < 4; nt++)
            acc[t][nt][0] = acc[t][nt][1] = acc[t][nt][2] = acc[t][nt][3] = 0.f;

    int cb = cg >> 1;
    const uint2* wbase = wfg + (cb << 11) + (((cg & 1) * 4) << 5) + lane;

#pragma unroll
    for (int kt = 0; kt < 8; kt++) {
        const uint2* wk = wbase + (kt << 8);
        uint2 bfr[4];
#pragma unroll
        for (int nt = 0; nt < 4; nt++) bfr[nt] = __ldg(wk + (nt << 5));
#pragma unroll
        for (int t = 0; t < 2; t++) {
            int row = rg * 32 + t * 16 + mr;
            uint32_t saddr = sbase + (uint32_t)(row * XW + kt * 8 + kw) * 4u;
            uint32_t ah[4];
            ldsm4(ah, saddr);
#pragma unroll
            for (int nt = 0; nt < 4; nt++)
                mma16816(acc[t][nt], ah, bfr[nt].x, bfr[nt].y);
        }
    }

    if (MODE == 1) {
#pragma unroll
        for (int t = 0; t < 2; t++) {
            int r0 = row0 + rg * 32 + t * 16 + gID;
            int r1 = r0 + 8;
#pragma unroll
            for (int nt = 0; nt < 4; nt++) {
                int c2 = cg * 16 + nt * 4 + tig;   // half2 column index
                if (r0 < n) Y[(size_t)r0 * 64 + c2] = __floats2half2_rn(acc[t][nt][0], acc[t][nt][1]);
                if (r1 < n) Y[(size_t)r1 * 64 + c2] = __floats2half2_rn(acc[t][nt][2], acc[t][nt][3]);
            }
        }
#pragma unroll
        for (int t = 0; t < 2; t++) {
            float el0 = 0.f, er0 = 0.f, el1v = 0.f, er1v = 0.f;
#pragma unroll
            for (int nt = 0; nt < 4; nt++) {
                int c2 = cg * 16 + nt * 4 + tig;
                float2 av = ((const float2*)attl)[c2];
                float2 rv = ((const float2*)attr)[c2];
                el0  += acc[t][nt][0] * av.x + acc[t][nt][1] * av.y;
                er0  += acc[t][nt][0] * rv.x + acc[t][nt][1] * rv.y;
                el1v += acc[t][nt][2] * av.x + acc[t][nt][3] * av.y;
                er1v += acc[t][nt][2] * rv.x + acc[t][nt][3] * rv.y;
            }
#pragma unroll
            for (int o = 1; o <= 2; o <<= 1) {
                el0  += __shfl_xor_sync(0xffffffffu, el0, o);
                er0  += __shfl_xor_sync(0xffffffffu, er0, o);
                el1v += __shfl_xor_sync(0xffffffffu, el1v, o);
                er1v += __shfl_xor_sync(0xffffffffu, er1v, o);
            }
            if (tig == 0) {
                int r0 = row0 + rg * 32 + t * 16 + gID;
                int r1 = r0 + 8;
                if (r0 < n) { elOut[r0 * 4 + cg] = el0;  erOut[r0 * 4 + cg] = er0; }
                if (r1 < n) { elOut[r1 * 4 + cg] = el1v; erOut[r1 * 4 + cg] = er1v; }
            }
        }
    } else {
#pragma unroll
        for (int t = 0; t < 2; t++) {
            float el0 = 0.f, er0 = 0.f, q0 = 0.f, el1v = 0.f, er1v = 0.f, q1v = 0.f;
#pragma unroll
            for (int nt = 0; nt < 4; nt++) {
                int c2 = cg * 16 + nt * 4 + tig;
                float2 av = ((const float2*)attl)[c2];
                float2 rv = ((const float2*)attr)[c2];
                float2 qv = ((const float2*)fcw)[c2];
                el0  += acc[t][nt][0] * av.x + acc[t][nt][1] * av.y;
                er0  += acc[t][nt][0] * rv.x + acc[t][nt][1] * rv.y;
                q0   += acc[t][nt][0] * qv.x + acc[t][nt][1] * qv.y;
                el1v += acc[t][nt][2] * av.x + acc[t][nt][3] * av.y;
                er1v += acc[t][nt][2] * rv.x + acc[t][nt][3] * rv.y;
                q1v  += acc[t][nt][2] * qv.x + acc[t][nt][3] * qv.y;
            }
#pragma unroll
            for (int o = 1; o <= 2; o <<= 1) {
                el0  += __shfl_xor_sync(0xffffffffu, el0, o);
                er0  += __shfl_xor_sync(0xffffffffu, er0, o);
                q0   += __shfl_xor_sync(0xffffffffu, q0, o);
                el1v += __shfl_xor_sync(0xffffffffu, el1v, o);
                er1v += __shfl_xor_sync(0xffffffffu, er1v, o);
                q1v  += __shfl_xor_sync(0xffffffffu, q1v, o);
            }
            if (tig == 0) {
                int r0 = row0 + rg * 32 + t * 16 + gID;
                int r1 = r0 + 8;
                if (r0 < n) {
                    atomicAdd(&eqOut[r0].x, el0);
                    atomicAdd(&eqOut[r0].y, q0);
                    atomicAdd(&erOut[r0], er0);
                }
                if (r1 < n) {
                    atomicAdd(&eqOut[r1].x, el1v);
                    atomicAdd(&eqOut[r1].y, q1v);
                    atomicAdd(&erOut[r1], er1v);
                }
            }
        }
    }
}

// ---------------- GAT aggregation, layer 1 (H=4), single pass, warp per node ------
// Full chunks of 8 edges run WITHOUT the data-dependent break; gathers issued in
// two groups of 4 (uu[4] => +8 regs only) for MLP=4. Tail chunk keeps break loop.
__global__ void k_agg1(const __half* __restrict__ feat, const float* __restrict__ bias,
                       uint2* __restrict__ out, int n) {
    int w = (blockIdx.x * blockDim.x + threadIdx.x) >> 5;
    int lane = threadIdx.x & 31;
    if (w >= n) return;
    int s0 = g_off[w], s1 = g_off[w + 1];
    int hw = lane & 3;    // weight-phase head
    int hf = lane >> 3;   // feature-phase head
    int c = lane >> 2;    // edge-in-chunk for weight phase
    float er_w = g_er1[w * 4 + hw];

    float dacc = 0.f;
    float4 acc = make_float4(0.f, 0.f, 0.f, 0.f);

    int base = s0;
    // full chunks (8 edges): no break -> loads batch
    for (; base + 8 <= s1; base += 8) {
        int s_c = g_csr[base + c];
        float wv = __expf(lrelu(g_el1[s_c * 4 + hw] + er_w));
        dacc += wv;
#pragma unroll
        for (int g2 = 0; g2 < 2; g2++) {
            uint2 uu[4];
            float wh[4];
#pragma unroll
            for (int k = 0; k < 4; k++) {
                int c2 = g2 * 4 + k;
                wh[k] = __shfl_sync(0xffffffffu, wv, c2 * 4 + hf);
                int s = __shfl_sync(0xffffffffu, s_c, c2 * 4);
                uu[k] = ((const uint2*)feat)[(size_t)s * 32 + lane];
            }
#pragma unroll
            for (int k = 0; k < 4; k++) {
                float2 f0 = __half22float2(*(__half2*)&uu[k].x);
                float2 f1 = __half22float2(*(__half2*)&uu[k].y);
                acc.x = fmaf(f0.x, wh[k], acc.x);
                acc.y = fmaf(f0.y, wh[k], acc.y);
                acc.z = fmaf(f1.x, wh[k], acc.z);
                acc.w = fmaf(f1.y, wh[k], acc.w);
            }
        }
    }
    // tail chunk (< 8 edges)
    if (base < s1) {
        int cnt = s1 - base;
        int s_c = 0;
        float wv = 0.f;
        if (c < cnt) {
            s_c = g_csr[base + c];
            wv = __expf(lrelu(g_el1[s_c * 4 + hw] + er_w));
        }
        dacc += wv;
#pragma unroll
        for (int c2 = 0; c2 < 8; c2++) {
            if (c2 >= cnt) break;
            float wh = __shfl_sync(0xffffffffu, wv, c2 * 4 + hf);
            int s = __shfl_sync(0xffffffffu, s_c, c2 * 4);
            uint2 u = ((const uint2*)feat)[(size_t)s * 32 + lane];
            float2 f0 = __half22float2(*(__half2*)&u.x);
            float2 f1 = __half22float2(*(__half2*)&u.y);
            acc.x = fmaf(f0.x, wh, acc.x);
            acc.y = fmaf(f0.y, wh, acc.y);
            acc.z = fmaf(f1.x, wh, acc.z);
            acc.w = fmaf(f1.y, wh, acc.w);
        }
    }

    dacc += __shfl_xor_sync(0xffffffffu, dacc, 4);
    dacc += __shfl_xor_sync(0xffffffffu, dacc, 8);
    dacc += __shfl_xor_sync(0xffffffffu, dacc, 16);
    float dh = __shfl_sync(0xffffffffu, dacc, hf);
    float inv = (dh > 0.f) ? (1.f / dh) : 0.f;

    float4 b = ((const float4*)bias)[lane];
    acc.x = fmaxf(fmaf(acc.x, inv, b.x), 0.f);
    acc.y = fmaxf(fmaf(acc.y, inv, b.y), 0.f);
    acc.z = fmaxf(fmaf(acc.z, inv, b.z), 0.f);
    acc.w = fmaxf(fmaf(acc.w, inv, b.w), 0.f);
    uint2 st;
    st.x = hfpack(acc.x, acc.y);
    st.y = hfpack(acc.z, acc.w);
    out[(size_t)w * 32 + lane] = st;
}

// ---------------- layer 2 aggregation (scalar) + classifier, half-warp per node ----
__global__ void k_agg2(float* __restrict__ out, int n) {
    int w = (blockIdx.x * blockDim.x + threadIdx.x) >> 4;
    int sub = threadIdx.x & 15;
    if (w >= n) return;
    int s0 = g_off[w], s1 = g_off[w + 1];
    float er = g_er2[w];

    float wsum = 0.f, wq = 0.f;
    for (int j = s0 + sub; j < s1; j += 16) {
        int s = g_csr[j];
        float2 v = g_eq[s];                       // (el2[s], q[s]) one 8B load
        float wv = __expf(lrelu(v.x + er));
        wsum += wv;
        wq = fmaf(wv, v.y, wq);
    }
#pragma unroll
    for (int o = 8; o; o >>= 1) {
        wsum += __shfl_xor_sync(0xffffffffu, wsum, o);
        wq   += __shfl_xor_sync(0xffffffffu, wq, o);
    }
    if (sub == 0) out[w] = ((wsum > 0.f) ? (wq / wsum) : 0.f) + g_cc;
}

// ---------------- launch ----------------
extern "C" void kernel_launch(void* const* d_in, const int* in_sizes, int n_in,
                              void* d_out, int out_size) {
    const float* features = (const float*)d_in[0];
    const float* W1 = (const float*)d_in[1];
    const float* al1 = (const float*)d_in[2];
    const float* ar1 = (const float*)d_in[3];
    const float* b1 = (const float*)d_in[4];
    const float* W2 = (const float*)d_in[5];
    const float* al2 = (const float*)d_in[6];
    const float* ar2 = (const float*)d_in[7];
    const float* b2 = (const float*)d_in[8];
    const float* fcW = (const float*)d_in[9];
    const float* fcb = (const float*)d_in[10];
    const float* thres = (const float*)d_in[11];
    const int* src = (const int*)d_in[12];
    const int* dst = (const int*)d_in[13];
    float* out = (float*)d_out;

    int n = in_sizes[0] / 128;
    int e = in_sizes[12];
    int nb = (n + 1023) / 1024;

    __half *p_feat1h, *p_h1h;
    float *p_el1, *p_er1, *p_er2;
    float2* p_eq;
    cudaGetSymbolAddress((void**)&p_feat1h, g_feat1h);
    cudaGetSymbolAddress((void**)&p_h1h, g_h1h);
    cudaGetSymbolAddress((void**)&p_el1, g_el1);
    cudaGetSymbolAddress((void**)&p_er1, g_er1);
    cudaGetSymbolAddress((void**)&p_eq, g_eq);
    cudaGetSymbolAddress((void**)&p_er2, g_er2);
    uint2 *p_wf1, *p_wf2;
    cudaGetSymbolAddress((void**)&p_wf1, g_wf1);
    cudaGetSymbolAddress((void**)&p_wf2, g_wf2);

    const int GEMM_SMEM = 128 * XW * 4;  // 34816
    cudaFuncSetAttribute(k_gemm_h<1>, cudaFuncAttributeMaxDynamicSharedMemorySize, GEMM_SMEM);
    cudaFuncSetAttribute(k_gemm_h<2>, cudaFuncAttributeMaxDynamicSharedMemorySize, GEMM_SMEM);

    int eb = (e + 255) / 256;
    int wblk = (n + 7) / 8;             // warp per node, 256-thread blocks
    int hblk = (n + 15) / 16;           // half-warp per node
    int gblk = (n + 127) / 128;         // gemm grid (512-thread CTAs)

    // fork-join resources (leaked intentionally: destroying during capture is illegal;
    // kernel_launch is called only a handful of times, never per-replay)
    cudaStream_t s2;
    cudaStreamCreateWithFlags(&s2, cudaStreamNonBlocking);
    cudaEvent_t e1, e2;
    cudaEventCreateWithFlags(&e1, cudaEventDisableTiming);
    cudaEventCreateWithFlags(&e2, cudaEventDisableTiming);

    // fork: CSR chain (hist -> scan -> fill) on s2 starts immediately;
    // main stream does wsetup -> GEMM1 concurrently.
    cudaEventRecord(e1, 0);
    cudaStreamWaitEvent(s2, e1, 0);
    k_hist<<<eb, 256, 0, s2>>>(dst, e);
    k_scan<<<nb, 1024, 0, s2>>>(n);
    k_fill<<<eb, 256, 0, s2>>>(src, dst, e, n);
    cudaEventRecord(e2, s2);             // CSR + zeroed eq/er2 ready

    k_wsetup<<<32, 256>>>(W1, W2, b2, fcW, fcb, thres);
    k_gemm_h<1><<<gblk, 512, GEMM_SMEM>>>(features, p_wf1, (__half2*)p_feat1h, n,
                                          al1, ar1, nullptr, p_el1, p_er1, nullptr);

    // join: agg1 needs GEMM1 outputs + CSR; gemm2's atomics need zeroed eq/er2
    cudaStreamWaitEvent(0, e2, 0);
    k_agg1<<<wblk, 256>>>(p_feat1h, b1, (uint2*)p_h1h, n);
    k_gemm_h<2><<<gblk, 512, GEMM_SMEM>>>(p_h1h, p_wf2, nullptr, n,
                                          al2, ar2, fcW, nullptr, p_er2, p_eq);
    k_agg2<<<hblk, 256>>>(out, n);
}

// round 15
// speedup vs baseline: 1.4564x; 1.0473x over previous
#include <cuda_runtime.h>
#include <cuda_fp16.h>
#include <stdint.h>
#include <math.h>

#define NMAX 100000
#define EMAX 1600000
#define NBMAX 128   // max scan blocks (n <= 131072)

// ---------------- scratch (device globals; no allocation allowed) ----------------
// Zero-state invariants: g_deg/g_tdesc zeroed by k_fill of the PREVIOUS run
// (statically zero on first run).
__device__ __half g_feat1h[NMAX * 128];  // x @ W1 (fp16 for cheap edge gathers)
__device__ float g_el1[NMAX * 4];
__device__ float g_er1[NMAX * 4];
__device__ float2 g_eq[NMAX];            // (el2, q) per node, computed in agg1 epilogue
__device__ float g_er2[NMAX];
__device__ float g_cc;                   // b2.fcW + fcb - thres
__device__ float4 g_uel[32];             // u_el = W2 @ al2^T  (128 floats as 32 float4)
__device__ float4 g_uer[32];             // u_er = W2 @ ar2^T
__device__ float4 g_uq[32];              // u_q  = W2 @ fcW
__device__ int g_deg[NMAX];
__device__ int g_off[NMAX + 1];
__device__ int g_ord[EMAX];              // per-edge ordinal within its dst (from hist)
__device__ volatile unsigned long long g_tdesc[NBMAX];  // scan lookback: status<<32 | value
__device__ int g_csr[EMAX];              // src node per dst-sorted slot
__device__ uint2 g_wf1[4096];            // W1 fp16 mma fragments (hi only)

// ---------------- fp16 helpers ----------------
__device__ __forceinline__ uint32_t hfpack(float a, float b) {
    __half2 t = __floats2half2_rn(a, b);
    return *reinterpret_cast<uint32_t*>(&t);
}

// ---------------- W1 fragments + layer-2 fold vectors + classifier constant -------
// uint2 = {b0_hi, b1_hi} for mma.m16n8k16 col-major B.
// u vectors: u[j] = sum_c W2[j*128+c] * v[c]  (feat2 = h1 @ W2, so el2 = h1 . u_el)
__global__ void k_wsetup(const float* __restrict__ W1, const float* __restrict__ W2,
                         const float* __restrict__ al2, const float* __restrict__ ar2,
                         const float* __restrict__ b2, const float* __restrict__ fcW,
                         const float* __restrict__ fcb, const float* __restrict__ thres) {
    int i = blockIdx.x * blockDim.x + threadIdx.x;
    if (i < 4096) {
        int lane = i & 31;
        int nt = (i >> 5) & 7;
        int kt = (i >> 8) & 7;
        int cb = i >> 11;
        int col = cb * 64 + nt * 8 + (lane >> 2);
        int tig = lane & 3;
        int k0 = kt * 16 + 2 * tig;
        uint2 o;
        o.x = hfpack(W1[k0 * 128 + col], W1[(k0 + 1) * 128 + col]);
        o.y = hfpack(W1[(k0 + 8) * 128 + col], W1[(k0 + 9) * 128 + col]);
        g_wf1[i] = o;
    }
    if (blockIdx.x == 0) {
        int j = threadIdx.x;
        if (j < 128) {
            const float* row = W2 + j * 128;
            float sel = 0.f, ser = 0.f, sq = 0.f;
#pragma unroll 4
            for (int c = 0; c < 128; c++) {
                float wv = row[c];
                sel = fmaf(wv, al2[c], sel);
                ser = fmaf(wv, ar2[c], ser);
                sq  = fmaf(wv, fcW[c], sq);
            }
            ((float*)g_uel)[j] = sel;
            ((float*)g_uer)[j] = ser;
            ((float*)g_uq)[j]  = sq;
        }
        if (threadIdx.x < 32) {
            int lane = threadIdx.x;
            float4 b = ((const float4*)b2)[lane];
            float4 wv = ((const float4*)fcW)[lane];
            float p = b.x * wv.x + b.y * wv.y + b.z * wv.z + b.w * wv.w;
            for (int o = 16; o; o >>= 1) p += __shfl_xor_sync(0xffffffffu, p, o);
            if (lane == 0) g_cc = p + fcb[0] - thres[0];
        }
    }
}

// ---------------- CSR build (side stream) ----------------
// hist: count degrees AND record each edge's ordinal within its destination.
__global__ void k_hist(const int* __restrict__ dst, int e) {
    int i = blockIdx.x * blockDim.x + threadIdx.x;
    if (i < e) g_ord[i] = atomicAdd(&g_deg[dst[i]], 1);
}

// single-pass exclusive scan with WARP-PARALLEL decoupled lookback.
__global__ void k_scan(int n) {
    __shared__ int s[1024];
    __shared__ int sexcl;
    int b = blockIdx.x, t = threadIdx.x;
    int g = b * 1024 + t;
    int v = (g < n) ? g_deg[g] : 0;
    s[t] = v;
    __syncthreads();
    for (int o = 1; o < 1024; o <<= 1) {
        int x = (t >= o) ? s[t - o] : 0;
        __syncthreads();
        s[t] += x;
        __syncthreads();
    }
    if (t < 32) {
        int total = s[1023];
        int excl = 0;
        if (b == 0) {
            if (t == 0) g_tdesc[0] = (2ull << 32) | (unsigned)total;
        } else {
            if (t == 0) g_tdesc[b] = (1ull << 32) | (unsigned)total;
            int p = b - 1;
            bool done = false;
            while (!done) {
                int idx = p - t;
                unsigned long long d = (idx >= 0) ? g_tdesc[idx] : (2ull << 32);
                unsigned st = (unsigned)(d >> 32);
                if (__all_sync(0xffffffffu, st != 0u)) {
                    unsigned m2 = __ballot_sync(0xffffffffu, st == 2u);
                    int f = (int)__ffs(m2) - 1;          // nearest inclusive-prefix lane
                    int lim = (f < 0) ? 31 : f;
                    int val = (t <= lim && idx >= 0) ? (int)(unsigned)d : 0;
#pragma unroll
                    for (int o = 16; o; o >>= 1) val += __shfl_xor_sync(0xffffffffu, val, o);
                    excl += val;
                    if (f >= 0) done = true; else p -= 32;
                }
            }
            if (t == 0) g_tdesc[b] = (2ull << 32) | (unsigned)(excl + total);
        }
        if (t == 0) sexcl = excl;
    }
    __syncthreads();
    int ex = sexcl + s[t] - v;
    if (g <= n) g_off[g] = ex;
}

// fill CSR: NO atomics (slot = off[dst] + ord), + restore zero-state
// (g_deg/g_tdesc for next run)
__global__ void k_fill(const int* __restrict__ src, const int* __restrict__ dst,
                       int e, int n) {
    int i = blockIdx.x * blockDim.x + threadIdx.x;
    if (i < e) {
        int d = dst[i];
        g_csr[g_off[d] + g_ord[i]] = src[i];
    }
    if (i < n) g_deg[i] = 0;
    if (i < NBMAX) g_tdesc[i] = 0ull;
}

// ---------------- mma / ldmatrix primitives ----------------
__device__ __forceinline__ void mma16816(float* c, const uint32_t* a, uint32_t b0, uint32_t b1) {
    asm volatile(
        "mma.sync.aligned.m16n8k16.row.col.f32.f16.f16.f32 "
        "{%0,%1,%2,%3}, {%4,%5,%6,%7}, {%8,%9}, {%0,%1,%2,%3};"
        : "+f"(c[0]), "+f"(c[1]), "+f"(c[2]), "+f"(c[3])
        : "r"(a[0]), "r"(a[1]), "r"(a[2]), "r"(a[3]), "r"(b0), "r"(b1));
}

__device__ __forceinline__ void ldsm4(uint32_t* r, uint32_t saddr) {
    asm volatile("ldmatrix.sync.aligned.m8n8.x4.shared.b16 {%0,%1,%2,%3}, [%4];"
                 : "=r"(r[0]), "=r"(r[1]), "=r"(r[2]), "=r"(r[3]) : "r"(saddr));
}

__device__ __forceinline__ float lrelu(float x) { return x >= 0.f ? x : 0.2f * x; }

#define XW 68   // padded X-tile row stride in 32-bit words

// ---------------- GEMM1: feat1h[n,128] = X[n,128] @ W1, + el1/er1 epilogue --------
// 512 threads (16 warps); CTA = 128 rows x 128 cols. Warp = 32 rows x 32 cols.
// A fp16, W fp16, fp32 acc. A frags via ldmatrix.x4. Head cg == warp col group.
__global__ __launch_bounds__(512, 2) void k_gemm1(
    const float* __restrict__ X, const uint2* __restrict__ wfg,
    __half2* __restrict__ Y, int n,
    const float* __restrict__ attl, const float* __restrict__ attr,
    float* __restrict__ elOut, float* __restrict__ erOut)
{
    extern __shared__ uint32_t xhi[];         // 128*XW words (34.8 KB)
    int tid = threadIdx.x;
    int row0 = blockIdx.x << 7;

    int nrow = n - row0;
    if (nrow > 128) nrow = 128;
    const float4* X4 = (const float4*)X;
    for (int i = tid; i < 4096; i += 512) {   // 128 rows x 32 float4
        int r = i >> 5, c = i & 31;
        float4 v = make_float4(0.f, 0.f, 0.f, 0.f);
        if (r < nrow) v = X4[(size_t)(row0 + r) * 32 + c];
        uint2 hi;
        hi.x = hfpack(v.x, v.y);
        hi.y = hfpack(v.z, v.w);
        *(uint2*)&xhi[r * XW + 2 * c] = hi;
    }
    __syncthreads();

    int warp = tid >> 5, lane = tid & 31;
    int cg = warp & 3;
    int rg = warp >> 2;
    int gID = lane >> 2, tig = lane & 3;

    uint32_t sbase;
    asm("{ .reg .u64 t; cvta.to.shared.u64 t, %1; cvt.u32.u64 %0, t; }"
        : "=r"(sbase) : "l"(xhi));
    int mr = (lane & 7) + ((lane >> 3) & 1) * 8;   // ldmatrix row within 16
    int kw = ((lane >> 4) & 1) * 4;                // +4 words for k8..15

    float acc[2][4][4];
#pragma unroll
    for (int t = 0; t < 2; t++)
#pragma unroll
        for (int nt = 0; nt < 4; nt++)
            acc[t][nt][0] = acc[t][nt][1] = acc[t][nt][2] = acc[t][nt][3] = 0.f;

    int cb = cg >> 1;
    const uint2* wbase = wfg + (cb << 11) + (((cg & 1) * 4) << 5) + lane;

#pragma unroll
    for (int kt = 0; kt < 8; kt++) {
        const uint2* wk = wbase + (kt << 8);
        uint2 bfr[4];
#pragma unroll
        for (int nt = 0; nt < 4; nt++) bfr[nt] = __ldg(wk + (nt << 5));
#pragma unroll
        for (int t = 0; t < 2; t++) {
            int row = rg * 32 + t * 16 + mr;
            uint32_t saddr = sbase + (uint32_t)(row * XW + kt * 8 + kw) * 4u;
            uint32_t ah[4];
            ldsm4(ah, saddr);
#pragma unroll
            for (int nt = 0; nt < 4; nt++)
                mma16816(acc[t][nt], ah, bfr[nt].x, bfr[nt].y);
        }
    }

#pragma unroll
    for (int t = 0; t < 2; t++) {
        int r0 = row0 + rg * 32 + t * 16 + gID;
        int r1 = r0 + 8;
#pragma unroll
        for (int nt = 0; nt < 4; nt++) {
            int c2 = cg * 16 + nt * 4 + tig;   // half2 column index
            if (r0 < n) Y[(size_t)r0 * 64 + c2] = __floats2half2_rn(acc[t][nt][0], acc[t][nt][1]);
            if (r1 < n) Y[(size_t)r1 * 64 + c2] = __floats2half2_rn(acc[t][nt][2], acc[t][nt][3]);
        }
    }
#pragma unroll
    for (int t = 0; t < 2; t++) {
        float el0 = 0.f, er0 = 0.f, el1v = 0.f, er1v = 0.f;
#pragma unroll
        for (int nt = 0; nt < 4; nt++) {
            int c2 = cg * 16 + nt * 4 + tig;
            float2 av = ((const float2*)attl)[c2];
            float2 rv = ((const float2*)attr)[c2];
            el0  += acc[t][nt][0] * av.x + acc[t][nt][1] * av.y;
            er0  += acc[t][nt][0] * rv.x + acc[t][nt][1] * rv.y;
            el1v += acc[t][nt][2] * av.x + acc[t][nt][3] * av.y;
            er1v += acc[t][nt][2] * rv.x + acc[t][nt][3] * rv.y;
        }
#pragma unroll
        for (int o = 1; o <= 2; o <<= 1) {
            el0  += __shfl_xor_sync(0xffffffffu, el0, o);
            er0  += __shfl_xor_sync(0xffffffffu, er0, o);
            el1v += __shfl_xor_sync(0xffffffffu, el1v, o);
            er1v += __shfl_xor_sync(0xffffffffu, er1v, o);
        }
        if (tig == 0) {
            int r0 = row0 + rg * 32 + t * 16 + gID;
            int r1 = r0 + 8;
            if (r0 < n) { elOut[r0 * 4 + cg] = el0;  erOut[r0 * 4 + cg] = er0; }
            if (r1 < n) { elOut[r1 * 4 + cg] = el1v; erOut[r1 * 4 + cg] = er1v; }
        }
    }
}

// ---------------- agg1: layer-1 GAT + DIRECT layer-2 scalar epilogue --------------
// Warp per node. After computing the fp32 h1 row (acc), fold the entire layer-2
// GEMM: el2 = h1.u_el, er2 = h1.u_er, q = h1.u_q (u = W2-folded vectors).
// h1 is NEVER materialized.
__global__ void k_agg1(const __half* __restrict__ feat, const float* __restrict__ bias,
                       int n) {
    int w = (blockIdx.x * blockDim.x + threadIdx.x) >> 5;
    int lane = threadIdx.x & 31;
    if (w >= n) return;
    int s0 = g_off[w], s1 = g_off[w + 1];
    int hw = lane & 3;    // weight-phase head
    int hf = lane >> 3;   // feature-phase head
    int c = lane >> 2;    // edge-in-chunk for weight phase
    float er_w = g_er1[w * 4 + hw];

    float dacc = 0.f;
    float4 acc = make_float4(0.f, 0.f, 0.f, 0.f);

    int base = s0;
    // full chunks (8 edges): no break -> loads batch (MLP=4)
    for (; base + 8 <= s1; base += 8) {
        int s_c = g_csr[base + c];
        float wv = __expf(lrelu(g_el1[s_c * 4 + hw] + er_w));
        dacc += wv;
#pragma unroll
        for (int g2 = 0; g2 < 2; g2++) {
            uint2 uu[4];
            float wh[4];
#pragma unroll
            for (int k = 0; k < 4; k++) {
                int c2 = g2 * 4 + k;
                wh[k] = __shfl_sync(0xffffffffu, wv, c2 * 4 + hf);
                int s = __shfl_sync(0xffffffffu, s_c, c2 * 4);
                uu[k] = ((const uint2*)feat)[(size_t)s * 32 + lane];
            }
#pragma unroll
            for (int k = 0; k < 4; k++) {
                float2 f0 = __half22float2(*(__half2*)&uu[k].x);
                float2 f1 = __half22float2(*(__half2*)&uu[k].y);
                acc.x = fmaf(f0.x, wh[k], acc.x);
                acc.y = fmaf(f0.y, wh[k], acc.y);
                acc.z = fmaf(f1.x, wh[k], acc.z);
                acc.w = fmaf(f1.y, wh[k], acc.w);
            }
        }
    }
    // tail chunk (< 8 edges)
    if (base < s1) {
        int cnt = s1 - base;
        int s_c = 0;
        float wv = 0.f;
        if (c < cnt) {
            s_c = g_csr[base + c];
            wv = __expf(lrelu(g_el1[s_c * 4 + hw] + er_w));
        }
        dacc += wv;
#pragma unroll
        for (int c2 = 0; c2 < 8; c2++) {
            if (c2 >= cnt) break;
            float wh = __shfl_sync(0xffffffffu, wv, c2 * 4 + hf);
            int s = __shfl_sync(0xffffffffu, s_c, c2 * 4);
            uint2 u = ((const uint2*)feat)[(size_t)s * 32 + lane];
            float2 f0 = __half22float2(*(__half2*)&u.x);
            float2 f1 = __half22float2(*(__half2*)&u.y);
            acc.x = fmaf(f0.x, wh, acc.x);
            acc.y = fmaf(f0.y, wh, acc.y);
            acc.z = fmaf(f1.x, wh, acc.z);
            acc.w = fmaf(f1.y, wh, acc.w);
        }
    }

    dacc += __shfl_xor_sync(0xffffffffu, dacc, 4);
    dacc += __shfl_xor_sync(0xffffffffu, dacc, 8);
    dacc += __shfl_xor_sync(0xffffffffu, dacc, 16);
    float dh = __shfl_sync(0xffffffffu, dacc, hf);
    float inv = (dh > 0.f) ? (1.f / dh) : 0.f;

    float4 b = ((const float4*)bias)[lane];
    acc.x = fmaxf(fmaf(acc.x, inv, b.x), 0.f);   // h1 row (fp32), dims lane*4..+3
    acc.y = fmaxf(fmaf(acc.y, inv, b.y), 0.f);
    acc.z = fmaxf(fmaf(acc.z, inv, b.z), 0.f);
    acc.w = fmaxf(fmaf(acc.w, inv, b.w), 0.f);

    // layer-2 fold: 3 dot products over the 128-dim row
    float4 ue = g_uel[lane], ur = g_uer[lane], uq = g_uq[lane];
    float pel = acc.x * ue.x + acc.y * ue.y + acc.z * ue.z + acc.w * ue.w;
    float per = acc.x * ur.x + acc.y * ur.y + acc.z * ur.z + acc.w * ur.w;
    float pq  = acc.x * uq.x + acc.y * uq.y + acc.z * uq.z + acc.w * uq.w;
#pragma unroll
    for (int o = 16; o; o >>= 1) {
        pel += __shfl_xor_sync(0xffffffffu, pel, o);
        per += __shfl_xor_sync(0xffffffffu, per, o);
        pq  += __shfl_xor_sync(0xffffffffu, pq, o);
    }
    if (lane == 0) {
        g_eq[w] = make_float2(pel, pq);
        g_er2[w] = per;
    }
}

// ---------------- layer 2 aggregation (scalar) + classifier, half-warp per node ----
__global__ void k_agg2(float* __restrict__ out, int n) {
    int w = (blockIdx.x * blockDim.x + threadIdx.x) >> 4;
    int sub = threadIdx.x & 15;
    if (w >= n) return;
    int s0 = g_off[w], s1 = g_off[w + 1];
    float er = g_er2[w];

    float wsum = 0.f, wq = 0.f;
    for (int j = s0 + sub; j < s1; j += 16) {
        int s = g_csr[j];
        float2 v = g_eq[s];                       // (el2[s], q[s]) one 8B load
        float wv = __expf(lrelu(v.x + er));
        wsum += wv;
        wq = fmaf(wv, v.y, wq);
    }
#pragma unroll
    for (int o = 8; o; o >>= 1) {
        wsum += __shfl_xor_sync(0xffffffffu, wsum, o);
        wq   += __shfl_xor_sync(0xffffffffu, wq, o);
    }
    if (sub == 0) out[w] = ((wsum > 0.f) ? (wq / wsum) : 0.f) + g_cc;
}

// ---------------- launch ----------------
extern "C" void kernel_launch(void* const* d_in, const int* in_sizes, int n_in,
                              void* d_out, int out_size) {
    const float* features = (const float*)d_in[0];
    const float* W1 = (const float*)d_in[1];
    const float* al1 = (const float*)d_in[2];
    const float* ar1 = (const float*)d_in[3];
    const float* b1 = (const float*)d_in[4];
    const float* W2 = (const float*)d_in[5];
    const float* al2 = (const float*)d_in[6];
    const float* ar2 = (const float*)d_in[7];
    const float* b2 = (const float*)d_in[8];
    const float* fcW = (const float*)d_in[9];
    const float* fcb = (const float*)d_in[10];
    const float* thres = (const float*)d_in[11];
    const int* src = (const int*)d_in[12];
    const int* dst = (const int*)d_in[13];
    float* out = (float*)d_out;

    int n = in_sizes[0] / 128;
    int e = in_sizes[12];
    int nb = (n + 1023) / 1024;

    __half* p_feat1h;
    float *p_el1, *p_er1;
    cudaGetSymbolAddress((void**)&p_feat1h, g_feat1h);
    cudaGetSymbolAddress((void**)&p_el1, g_el1);
    cudaGetSymbolAddress((void**)&p_er1, g_er1);
    uint2* p_wf1;
    cudaGetSymbolAddress((void**)&p_wf1, g_wf1);

    const int GEMM_SMEM = 128 * XW * 4;  // 34816
    cudaFuncSetAttribute(k_gemm1, cudaFuncAttributeMaxDynamicSharedMemorySize, GEMM_SMEM);

    int eb = (e + 255) / 256;
    int wblk = (n + 7) / 8;             // warp per node, 256-thread blocks
    int hblk = (n + 15) / 16;           // half-warp per node
    int gblk = (n + 127) / 128;         // gemm grid (512-thread CTAs)

    // fork-join resources (leaked intentionally: destroying during capture is illegal;
    // kernel_launch is called only a handful of times, never per-replay)
    cudaStream_t s2;
    cudaStreamCreateWithFlags(&s2, cudaStreamNonBlocking);
    cudaEvent_t e1, e2;
    cudaEventCreateWithFlags(&e1, cudaEventDisableTiming);
    cudaEventCreateWithFlags(&e2, cudaEventDisableTiming);

    // fork: CSR chain (hist -> scan -> fill) on s2 starts immediately;
    // main stream does wsetup -> GEMM1 concurrently.
    cudaEventRecord(e1, 0);
    cudaStreamWaitEvent(s2, e1, 0);
    k_hist<<<eb, 256, 0, s2>>>(dst, e);
    k_scan<<<nb, 1024, 0, s2>>>(n);
    k_fill<<<eb, 256, 0, s2>>>(src, dst, e, n);
    cudaEventRecord(e2, s2);             // CSR ready

    k_wsetup<<<16, 256>>>(W1, W2, al2, ar2, b2, fcW, fcb, thres);
    k_gemm1<<<gblk, 512, GEMM_SMEM>>>(features, p_wf1, (__half2*)p_feat1h, n,
                                      al1, ar1, p_el1, p_er1);

    // join: agg1 needs GEMM1 outputs + CSR
    cudaStreamWaitEvent(0, e2, 0);
    k_agg1<<<wblk, 256>>>(p_feat1h, b1, n);
    k_agg2<<<hblk, 256>>>(out, n);
}

// round 16
// speedup vs baseline: 1.5892x; 1.0912x over previous
#include <cuda_runtime.h>
#include <cuda_fp16.h>
#include <stdint.h>
#include <math.h>

#define NMAX 100000
#define EMAX 1600000
#define NBMAX 128   // max scan blocks (n <= 131072)

// ---------------- scratch (device globals; no allocation allowed) ----------------
// Zero-state invariants: g_deg/g_tdesc zeroed by k_fill of the PREVIOUS run
// (statically zero on first run).
__device__ __half g_feat1h[NMAX * 128];  // x @ W1 (fp16 for cheap edge gathers)
__device__ float g_el1[NMAX * 4];
__device__ float g_er1[NMAX * 4];
__device__ float2 g_eq[NMAX];            // (el2, q) per node, computed in agg1 epilogue
__device__ float g_er2[NMAX];
__device__ float g_cc;                   // b2.fcW + fcb - thres
__device__ float4 g_uel[32];             // u_el = W2 @ al2^T  (128 floats as 32 float4)
__device__ float4 g_uer[32];             // u_er = W2 @ ar2^T
__device__ float4 g_uq[32];              // u_q  = W2 @ fcW
__device__ int g_deg[NMAX];
__device__ int g_off[NMAX + 1];
__device__ int g_ord[EMAX];              // per-edge ordinal within its dst (from hist)
__device__ volatile unsigned long long g_tdesc[NBMAX];  // scan lookback: status<<32 | value
__device__ int g_csr[EMAX];              // src node per dst-sorted slot
__device__ uint2 g_wf1[4096];            // W1 fp16 mma fragments (hi only)

// ---------------- fp16 helpers ----------------
__device__ __forceinline__ uint32_t hfpack(float a, float b) {
    __half2 t = __floats2half2_rn(a, b);
    return *reinterpret_cast<uint32_t*>(&t);
}

// ---------------- W1 fragments + layer-2 fold vectors + classifier constant -------
// uint2 = {b0_hi, b1_hi} for mma.m16n8k16 col-major B.
// u vectors (WARP per output j, coalesced): u[j] = sum_c W2[j*128+c] * v[c].
__global__ void k_wsetup(const float* __restrict__ W1, const float* __restrict__ W2,
                         const float* __restrict__ al2, const float* __restrict__ ar2,
                         const float* __restrict__ b2, const float* __restrict__ fcW,
                         const float* __restrict__ fcb, const float* __restrict__ thres) {
    int i = blockIdx.x * blockDim.x + threadIdx.x;
    if (i < 4096) {
        int lane = i & 31;
        int nt = (i >> 5) & 7;
        int kt = (i >> 8) & 7;
        int cb = i >> 11;
        int col = cb * 64 + nt * 8 + (lane >> 2);
        int tig = lane & 3;
        int k0 = kt * 16 + 2 * tig;
        uint2 o;
        o.x = hfpack(W1[k0 * 128 + col], W1[(k0 + 1) * 128 + col]);
        o.y = hfpack(W1[(k0 + 8) * 128 + col], W1[(k0 + 9) * 128 + col]);
        g_wf1[i] = o;
    } else if (i < 8192) {
        // warp per output element j (128 warps): coalesced W2 row reads
        int j = (i - 4096) >> 5;
        int lane = i & 31;
        const float* row = W2 + j * 128;
        float sel = 0.f, ser = 0.f, sq = 0.f;
#pragma unroll
        for (int k = 0; k < 4; k++) {
            int c = lane + k * 32;
            float wv = row[c];
            sel = fmaf(wv, al2[c], sel);
            ser = fmaf(wv, ar2[c], ser);
            sq  = fmaf(wv, fcW[c], sq);
        }
#pragma unroll
        for (int o = 16; o; o >>= 1) {
            sel += __shfl_xor_sync(0xffffffffu, sel, o);
            ser += __shfl_xor_sync(0xffffffffu, ser, o);
            sq  += __shfl_xor_sync(0xffffffffu, sq, o);
        }
        if (lane == 0) {
            ((float*)g_uel)[j] = sel;
            ((float*)g_uer)[j] = ser;
            ((float*)g_uq)[j]  = sq;
        }
    } else if (i < 8224) {
        // warp 257: classifier constant
        int lane = i & 31;
        float4 b = ((const float4*)b2)[lane];
        float4 wv = ((const float4*)fcW)[lane];
        float p = b.x * wv.x + b.y * wv.y + b.z * wv.z + b.w * wv.w;
        for (int o = 16; o; o >>= 1) p += __shfl_xor_sync(0xffffffffu, p, o);
        if (lane == 0) g_cc = p + fcb[0] - thres[0];
    }
}

// ---------------- CSR build (side stream) ----------------
// hist: count degrees AND record each edge's ordinal within its destination.
__global__ void k_hist(const int* __restrict__ dst, int e) {
    int i = blockIdx.x * blockDim.x + threadIdx.x;
    if (i < e) g_ord[i] = atomicAdd(&g_deg[dst[i]], 1);
}

// single-pass exclusive scan with WARP-PARALLEL decoupled lookback.
__global__ void k_scan(int n) {
    __shared__ int s[1024];
    __shared__ int sexcl;
    int b = blockIdx.x, t = threadIdx.x;
    int g = b * 1024 + t;
    int v = (g < n) ? g_deg[g] : 0;
    s[t] = v;
    __syncthreads();
    for (int o = 1; o < 1024; o <<= 1) {
        int x = (t >= o) ? s[t - o] : 0;
        __syncthreads();
        s[t] += x;
        __syncthreads();
    }
    if (t < 32) {
        int total = s[1023];
        int excl = 0;
        if (b == 0) {
            if (t == 0) g_tdesc[0] = (2ull << 32) | (unsigned)total;
        } else {
            if (t == 0) g_tdesc[b] = (1ull << 32) | (unsigned)total;
            int p = b - 1;
            bool done = false;
            while (!done) {
                int idx = p - t;
                unsigned long long d = (idx >= 0) ? g_tdesc[idx] : (2ull << 32);
                unsigned st = (unsigned)(d >> 32);
                if (__all_sync(0xffffffffu, st != 0u)) {
                    unsigned m2 = __ballot_sync(0xffffffffu, st == 2u);
                    int f = (int)__ffs(m2) - 1;          // nearest inclusive-prefix lane
                    int lim = (f < 0) ? 31 : f;
                    int val = (t <= lim && idx >= 0) ? (int)(unsigned)d : 0;
#pragma unroll
                    for (int o = 16; o; o >>= 1) val += __shfl_xor_sync(0xffffffffu, val, o);
                    excl += val;
                    if (f >= 0) done = true; else p -= 32;
                }
            }
            if (t == 0) g_tdesc[b] = (2ull << 32) | (unsigned)(excl + total);
        }
        if (t == 0) sexcl = excl;
    }
    __syncthreads();
    int ex = sexcl + s[t] - v;
    if (g <= n) g_off[g] = ex;
}

// fill CSR: NO atomics (slot = off[dst] + ord), + restore zero-state
// (g_deg/g_tdesc for next run)
__global__ void k_fill(const int* __restrict__ src, const int* __restrict__ dst,
                       int e, int n) {
    int i = blockIdx.x * blockDim.x + threadIdx.x;
    if (i < e) {
        int d = dst[i];
        g_csr[g_off[d] + g_ord[i]] = src[i];
    }
    if (i < n) g_deg[i] = 0;
    if (i < NBMAX) g_tdesc[i] = 0ull;
}

// ---------------- mma / ldmatrix primitives ----------------
__device__ __forceinline__ void mma16816(float* c, const uint32_t* a, uint32_t b0, uint32_t b1) {
    asm volatile(
        "mma.sync.aligned.m16n8k16.row.col.f32.f16.f16.f32 "
        "{%0,%1,%2,%3}, {%4,%5,%6,%7}, {%8,%9}, {%0,%1,%2,%3};"
        : "+f"(c[0]), "+f"(c[1]), "+f"(c[2]), "+f"(c[3])
        : "r"(a[0]), "r"(a[1]), "r"(a[2]), "r"(a[3]), "r"(b0), "r"(b1));
}

__device__ __forceinline__ void ldsm4(uint32_t* r, uint32_t saddr) {
    asm volatile("ldmatrix.sync.aligned.m8n8.x4.shared.b16 {%0,%1,%2,%3}, [%4];"
                 : "=r"(r[0]), "=r"(r[1]), "=r"(r[2]), "=r"(r[3]) : "r"(saddr));
}

__device__ __forceinline__ float lrelu(float x) { return x >= 0.f ? x : 0.2f * x; }

#define XW 68   // padded X-tile row stride in 32-bit words

// ---------------- GEMM1: feat1h[n,128] = X[n,128] @ W1, + el1/er1 epilogue --------
// 512 threads (16 warps); CTA = 128 rows x 128 cols. Warp = 32 rows x 32 cols.
// A fp16, W fp16, fp32 acc. A frags via ldmatrix.x4. Head cg == warp col group.
__global__ __launch_bounds__(512, 2) void k_gemm1(
    const float* __restrict__ X, const uint2* __restrict__ wfg,
    __half2* __restrict__ Y, int n,
    const float* __restrict__ attl, const float* __restrict__ attr,
    float* __restrict__ elOut, float* __restrict__ erOut)
{
    extern __shared__ uint32_t xhi[];         // 128*XW words (34.8 KB)
    int tid = threadIdx.x;
    int row0 = blockIdx.x << 7;

    int nrow = n - row0;
    if (nrow > 128) nrow = 128;
    const float4* X4 = (const float4*)X;
    for (int i = tid; i < 4096; i += 512) {   // 128 rows x 32 float4
        int r = i >> 5, c = i & 31;
        float4 v = make_float4(0.f, 0.f, 0.f, 0.f);
        if (r < nrow) v = X4[(size_t)(row0 + r) * 32 + c];
        uint2 hi;
        hi.x = hfpack(v.x, v.y);
        hi.y = hfpack(v.z, v.w);
        *(uint2*)&xhi[r * XW + 2 * c] = hi;
    }
    __syncthreads();

    int warp = tid >> 5, lane = tid & 31;
    int cg = warp & 3;
    int rg = warp >> 2;
    int gID = lane >> 2, tig = lane & 3;

    uint32_t sbase;
    asm("{ .reg .u64 t; cvta.to.shared.u64 t, %1; cvt.u32.u64 %0, t; }"
        : "=r"(sbase) : "l"(xhi));
    int mr = (lane & 7) + ((lane >> 3) & 1) * 8;   // ldmatrix row within 16
    int kw = ((lane >> 4) & 1) * 4;                // +4 words for k8..15

    float acc[2][4][4];
#pragma unroll
    for (int t = 0; t < 2; t++)
#pragma unroll
        for (int nt = 0; nt < 4; nt++)
            acc[t][nt][0] = acc[t][nt][1] = acc[t][nt][2] = acc[t][nt][3] = 0.f;

    int cb = cg >> 1;
    const uint2* wbase = wfg + (cb << 11) + (((cg & 1) * 4) << 5) + lane;

#pragma unroll
    for (int kt = 0; kt < 8; kt++) {
        const uint2* wk = wbase + (kt << 8);
        uint2 bfr[4];
#pragma unroll
        for (int nt = 0; nt < 4; nt++) bfr[nt] = __ldg(wk + (nt << 5));
#pragma unroll
        for (int t = 0; t < 2; t++) {
            int row = rg * 32 + t * 16 + mr;
            uint32_t saddr = sbase + (uint32_t)(row * XW + kt * 8 + kw) * 4u;
            uint32_t ah[4];
            ldsm4(ah, saddr);
#pragma unroll
            for (int nt = 0; nt < 4; nt++)
                mma16816(acc[t][nt], ah, bfr[nt].x, bfr[nt].y);
        }
    }

#pragma unroll
    for (int t = 0; t < 2; t++) {
        int r0 = row0 + rg * 32 + t * 16 + gID;
        int r1 = r0 + 8;
#pragma unroll
        for (int nt = 0; nt < 4; nt++) {
            int c2 = cg * 16 + nt * 4 + tig;   // half2 column index
            if (r0 < n) Y[(size_t)r0 * 64 + c2] = __floats2half2_rn(acc[t][nt][0], acc[t][nt][1]);
            if (r1 < n) Y[(size_t)r1 * 64 + c2] = __floats2half2_rn(acc[t][nt][2], acc[t][nt][3]);
        }
    }
#pragma unroll
    for (int t = 0; t < 2; t++) {
        float el0 = 0.f, er0 = 0.f, el1v = 0.f, er1v = 0.f;
#pragma unroll
        for (int nt = 0; nt < 4; nt++) {
            int c2 = cg * 16 + nt * 4 + tig;
            float2 av = ((const float2*)attl)[c2];
            float2 rv = ((const float2*)attr)[c2];
            el0  += acc[t][nt][0] * av.x + acc[t][nt][1] * av.y;
            er0  += acc[t][nt][0] * rv.x + acc[t][nt][1] * rv.y;
            el1v += acc[t][nt][2] * av.x + acc[t][nt][3] * av.y;
            er1v += acc[t][nt][2] * rv.x + acc[t][nt][3] * rv.y;
        }
#pragma unroll
        for (int o = 1; o <= 2; o <<= 1) {
            el0  += __shfl_xor_sync(0xffffffffu, el0, o);
            er0  += __shfl_xor_sync(0xffffffffu, er0, o);
            el1v += __shfl_xor_sync(0xffffffffu, el1v, o);
            er1v += __shfl_xor_sync(0xffffffffu, er1v, o);
        }
        if (tig == 0) {
            int r0 = row0 + rg * 32 + t * 16 + gID;
            int r1 = r0 + 8;
            if (r0 < n) { elOut[r0 * 4 + cg] = el0;  erOut[r0 * 4 + cg] = er0; }
            if (r1 < n) { elOut[r1 * 4 + cg] = el1v; erOut[r1 * 4 + cg] = er1v; }
        }
    }
}

// ---------------- agg1: layer-1 GAT + DIRECT layer-2 scalar epilogue --------------
// Warp per node. After computing the fp32 h1 row (acc), fold the entire layer-2
// GEMM: el2 = h1.u_el, er2 = h1.u_er, q = h1.u_q (u = W2-folded vectors).
// h1 is NEVER materialized.
__global__ void k_agg1(const __half* __restrict__ feat, const float* __restrict__ bias,
                       int n) {
    int w = (blockIdx.x * blockDim.x + threadIdx.x) >> 5;
    int lane = threadIdx.x & 31;
    if (w >= n) return;
    int s0 = g_off[w], s1 = g_off[w + 1];
    int hw = lane & 3;    // weight-phase head
    int hf = lane >> 3;   // feature-phase head
    int c = lane >> 2;    // edge-in-chunk for weight phase
    float er_w = g_er1[w * 4 + hw];

    float dacc = 0.f;
    float4 acc = make_float4(0.f, 0.f, 0.f, 0.f);

    int base = s0;
    // full chunks (8 edges): no break -> loads batch (MLP=4)
    for (; base + 8 <= s1; base += 8) {
        int s_c = g_csr[base + c];
        float wv = __expf(lrelu(g_el1[s_c * 4 + hw] + er_w));
        dacc += wv;
#pragma unroll
        for (int g2 = 0; g2 < 2; g2++) {
            uint2 uu[4];
            float wh[4];
#pragma unroll
            for (int k = 0; k < 4; k++) {
                int c2 = g2 * 4 + k;
                wh[k] = __shfl_sync(0xffffffffu, wv, c2 * 4 + hf);
                int s = __shfl_sync(0xffffffffu, s_c, c2 * 4);
                uu[k] = ((const uint2*)feat)[(size_t)s * 32 + lane];
            }
#pragma unroll
            for (int k = 0; k < 4; k++) {
                float2 f0 = __half22float2(*(__half2*)&uu[k].x);
                float2 f1 = __half22float2(*(__half2*)&uu[k].y);
                acc.x = fmaf(f0.x, wh[k], acc.x);
                acc.y = fmaf(f0.y, wh[k], acc.y);
                acc.z = fmaf(f1.x, wh[k], acc.z);
                acc.w = fmaf(f1.y, wh[k], acc.w);
            }
        }
    }
    // tail chunk (< 8 edges)
    if (base < s1) {
        int cnt = s1 - base;
        int s_c = 0;
        float wv = 0.f;
        if (c < cnt) {
            s_c = g_csr[base + c];
            wv = __expf(lrelu(g_el1[s_c * 4 + hw] + er_w));
        }
        dacc += wv;
#pragma unroll
        for (int c2 = 0; c2 < 8; c2++) {
            if (c2 >= cnt) break;
            float wh = __shfl_sync(0xffffffffu, wv, c2 * 4 + hf);
            int s = __shfl_sync(0xffffffffu, s_c, c2 * 4);
            uint2 u = ((const uint2*)feat)[(size_t)s * 32 + lane];
            float2 f0 = __half22float2(*(__half2*)&u.x);
            float2 f1 = __half22float2(*(__half2*)&u.y);
            acc.x = fmaf(f0.x, wh, acc.x);
            acc.y = fmaf(f0.y, wh, acc.y);
            acc.z = fmaf(f1.x, wh, acc.z);
            acc.w = fmaf(f1.y, wh, acc.w);
        }
    }

    dacc += __shfl_xor_sync(0xffffffffu, dacc, 4);
    dacc += __shfl_xor_sync(0xffffffffu, dacc, 8);
    dacc += __shfl_xor_sync(0xffffffffu, dacc, 16);
    float dh = __shfl_sync(0xffffffffu, dacc, hf);
    float inv = (dh > 0.f) ? (1.f / dh) : 0.f;

    float4 b = ((const float4*)bias)[lane];
    acc.x = fmaxf(fmaf(acc.x, inv, b.x), 0.f);   // h1 row (fp32), dims lane*4..+3
    acc.y = fmaxf(fmaf(acc.y, inv, b.y), 0.f);
    acc.z = fmaxf(fmaf(acc.z, inv, b.z), 0.f);
    acc.w = fmaxf(fmaf(acc.w, inv, b.w), 0.f);

    // layer-2 fold: 3 dot products over the 128-dim row
    float4 ue = g_uel[lane], ur = g_uer[lane], uq = g_uq[lane];
    float pel = acc.x * ue.x + acc.y * ue.y + acc.z * ue.z + acc.w * ue.w;
    float per = acc.x * ur.x + acc.y * ur.y + acc.z * ur.z + acc.w * ur.w;
    float pq  = acc.x * uq.x + acc.y * uq.y + acc.z * uq.z + acc.w * uq.w;
#pragma unroll
    for (int o = 16; o; o >>= 1) {
        pel += __shfl_xor_sync(0xffffffffu, pel, o);
        per += __shfl_xor_sync(0xffffffffu, per, o);
        pq  += __shfl_xor_sync(0xffffffffu, pq, o);
    }
    if (lane == 0) {
        g_eq[w] = make_float2(pel, pq);
        g_er2[w] = per;
    }
}

// ---------------- layer 2 aggregation (scalar) + classifier, half-warp per node ----
__global__ void k_agg2(float* __restrict__ out, int n) {
    int w = (blockIdx.x * blockDim.x + threadIdx.x) >> 4;
    int sub = threadIdx.x & 15;
    if (w >= n) return;
    int s0 = g_off[w], s1 = g_off[w + 1];
    float er = g_er2[w];

    float wsum = 0.f, wq = 0.f;
    for (int j = s0 + sub; j < s1; j += 16) {
        int s = g_csr[j];
        float2 v = g_eq[s];                       // (el2[s], q[s]) one 8B load
        float wv = __expf(lrelu(v.x + er));
        wsum += wv;
        wq = fmaf(wv, v.y, wq);
    }
#pragma unroll
    for (int o = 8; o; o >>= 1) {
        wsum += __shfl_xor_sync(0xffffffffu, wsum, o);
        wq   += __shfl_xor_sync(0xffffffffu, wq, o);
    }
    if (sub == 0) out[w] = ((wsum > 0.f) ? (wq / wsum) : 0.f) + g_cc;
}

// ---------------- launch ----------------
extern "C" void kernel_launch(void* const* d_in, const int* in_sizes, int n_in,
                              void* d_out, int out_size) {
    const float* features = (const float*)d_in[0];
    const float* W1 = (const float*)d_in[1];
    const float* al1 = (const float*)d_in[2];
    const float* ar1 = (const float*)d_in[3];
    const float* b1 = (const float*)d_in[4];
    const float* W2 = (const float*)d_in[5];
    const float* al2 = (const float*)d_in[6];
    const float* ar2 = (const float*)d_in[7];
    const float* b2 = (const float*)d_in[8];
    const float* fcW = (const float*)d_in[9];
    const float* fcb = (const float*)d_in[10];
    const float* thres = (const float*)d_in[11];
    const int* src = (const int*)d_in[12];
    const int* dst = (const int*)d_in[13];
    float* out = (float*)d_out;

    int n = in_sizes[0] / 128;
    int e = in_sizes[12];
    int nb = (n + 1023) / 1024;

    __half* p_feat1h;
    float *p_el1, *p_er1;
    cudaGetSymbolAddress((void**)&p_feat1h, g_feat1h);
    cudaGetSymbolAddress((void**)&p_el1, g_el1);
    cudaGetSymbolAddress((void**)&p_er1, g_er1);
    uint2* p_wf1;
    cudaGetSymbolAddress((void**)&p_wf1, g_wf1);

    const int GEMM_SMEM = 128 * XW * 4;  // 34816
    cudaFuncSetAttribute(k_gemm1, cudaFuncAttributeMaxDynamicSharedMemorySize, GEMM_SMEM);

    int eb = (e + 255) / 256;
    int wblk = (n + 7) / 8;             // warp per node, 256-thread blocks
    int hblk = (n + 15) / 16;           // half-warp per node
    int gblk = (n + 127) / 128;         // gemm grid (512-thread CTAs)

    // fork-join resources (leaked intentionally: destroying during capture is illegal;
    // kernel_launch is called only a handful of times, never per-replay)
    cudaStream_t s2;
    cudaStreamCreateWithFlags(&s2, cudaStreamNonBlocking);
    cudaEvent_t e1, e2;
    cudaEventCreateWithFlags(&e1, cudaEventDisableTiming);
    cudaEventCreateWithFlags(&e2, cudaEventDisableTiming);

    // fork: CSR chain (hist -> scan -> fill) on s2 starts immediately;
    // main stream does wsetup -> GEMM1 concurrently.
    cudaEventRecord(e1, 0);
    cudaStreamWaitEvent(s2, e1, 0);
    k_hist<<<eb, 256, 0, s2>>>(dst, e);
    k_scan<<<nb, 1024, 0, s2>>>(n);
    k_fill<<<eb, 256, 0, s2>>>(src, dst, e, n);
    cudaEventRecord(e2, s2);             // CSR ready

    k_wsetup<<<33, 256>>>(W1, W2, al2, ar2, b2, fcW, fcb, thres);
    k_gemm1<<<gblk, 512, GEMM_SMEM>>>(features, p_wf1, (__half2*)p_feat1h, n,
                                      al1, ar1, p_el1, p_er1);

    // join: agg1 needs GEMM1 outputs + CSR
    cudaStreamWaitEvent(0, e2, 0);
    k_agg1<<<wblk, 256>>>(p_feat1h, b1, n);
    k_agg2<<<hblk, 256>>>(out, n);
}